// round 1
// baseline (speedup 1.0000x reference)
#include <cuda_runtime.h>
#include <math.h>

// Problem constants (fixed by dataset)
#define NB    512     // graphs
#define NPG   128     // nodes per graph
#define EPG   2048    // edges per graph
#define HID   128
#define KSEL  64

// Shared memory layout (in floats)
constexpr int XS_STRIDE = 129;          // xsT [128][129]
constexpr int HP_STRIDE = 132;          // hp/AGG [128][132], 528B rows (16B aligned)
constexpr int OFF_R0   = 0;             // xsT (GEMM phase) / AGG (later)
constexpr int SZ_R0    = HP_STRIDE * 128;         // 16896
constexpr int OFF_W1   = OFF_R0 + SZ_R0;          // 16896
constexpr int SZ_W1    = 128 * 128;               // 16384
constexpr int OFF_HP   = OFF_W1 + SZ_W1;          // 33280
constexpr int SZ_HP    = HP_STRIDE * 128;         // 16896
constexpr int OFF_MISC = OFF_HP + SZ_HP;          // 50176
// misc: ssrc(u16 x2048 = 1024 floats) + 8 arrays of 128
constexpr int MISC_FLOATS = 1024 + 8 * 128;       // 2048
constexpr int SMEM_FLOATS = OFF_MISC + MISC_FLOATS;
constexpr int SMEM_BYTES  = SMEM_FLOATS * 4;      // 208,896 bytes

extern __shared__ float S[];

__global__ void __launch_bounds__(256, 1) sagpool_fused_kernel(
    const float* __restrict__ x,
    const int*   __restrict__ esrc,   // edge_index[0]
    const int*   __restrict__ edst,   // edge_index[1]
    const float* __restrict__ W1,
    const float* __restrict__ b1,
    const float* __restrict__ Ws,
    const float* __restrict__ bs,
    const float* __restrict__ Wlin,
    const float* __restrict__ blin,
    float*       __restrict__ out)
{
    const int g = blockIdx.x;
    const int t = threadIdx.x;
    const int lane = t & 31;
    const int warp = t >> 5;

    float* xsT = S + OFF_R0;                 // [128][129] x transposed (k-major)
    float* AGG = S + OFF_R0;                 // [128][132] final h (reuses xsT+part of W1s)
    float* W1s = S + OFF_W1;                 // [128][128]
    float* hp  = S + OFF_HP;                 // [128][132] pre-aggregation h = x@W1
    unsigned short* ssrc = (unsigned short*)(S + OFF_MISC);  // 2048 u16
    int*   cnt    = (int*)(S + OFF_MISC + 1024);
    int*   offs   = cnt   + 128;
    int*   pos    = offs  + 128;
    float* rinv   = (float*)(pos + 128);
    float* tval   = rinv  + 128;
    float* score  = tval  + 128;
    float* wsel   = score + 128;
    float* pooled = wsel  + 128;

    // ---- Phase A: degree counting (self-loop included) + edge load ----
    if (t < 128) cnt[t] = 1;            // self loop
    __syncthreads();

    const int ebase = g * EPG;
    int sloc[8], dloc[8];
#pragma unroll
    for (int e = 0; e < 8; e++) {
        int ei = ebase + t + e * 256;           // coalesced
        sloc[e] = esrc[ei] & (NPG - 1);         // nodes are g*128 + local
        dloc[e] = edst[ei] & (NPG - 1);
        atomicAdd(&cnt[dloc[e]], 1);
    }

    // ---- concurrently: load x tile (transposed) and W1 to smem ----
    const float* xg = x + (size_t)g * NPG * HID;
    for (int idx = t; idx < 128 * 128; idx += 256) {
        int i = idx >> 7, k = idx & 127;
        xsT[k * XS_STRIDE + i] = xg[idx];
        W1s[idx] = W1[idx];
    }
    __syncthreads();

    // ---- rinv + exclusive prefix sum of incoming-edge counts ----
    if (t < 128) {
        rinv[t] = rsqrtf((float)cnt[t]);
        offs[t] = cnt[t] - 1;                  // incoming (non-self) count
    }
    __syncthreads();
    for (int sh = 1; sh < 128; sh <<= 1) {     // Hillis-Steele inclusive scan
        int v = 0;
        if (t < 128 && t >= sh) v = offs[t - sh];
        __syncthreads();
        if (t < 128) offs[t] += v;
        __syncthreads();
    }
    if (t < 128) {
        int excl = offs[t] - (cnt[t] - 1);
        pos[t]  = excl;
    }
    __syncthreads();
    if (t < 128) offs[t] = pos[t];             // keep exclusive start
    __syncthreads();

    // ---- counting-sort scatter: group edge sources by dst ----
#pragma unroll
    for (int e = 0; e < 8; e++) {
        int p = atomicAdd(&pos[dloc[e]], 1);
        ssrc[p] = (unsigned short)sloc[e];
    }
    // (readers of ssrc sync below, after GEMM)

    // ---- Phase C: GEMM hp = x_g @ W1  (128x128x128, register tiles) ----
    const int tx = t & 15, ty = t >> 4;
    float acc[8][8];
#pragma unroll
    for (int r = 0; r < 8; r++)
#pragma unroll
        for (int c = 0; c < 8; c++) acc[r][c] = 0.f;

#pragma unroll 4
    for (int k = 0; k < 128; k++) {
        float a[8], b[8];
#pragma unroll
        for (int r = 0; r < 8; r++) a[r] = xsT[k * XS_STRIDE + ty + 16 * r];
#pragma unroll
        for (int c = 0; c < 8; c++) b[c] = W1s[k * 128 + tx + 16 * c];
#pragma unroll
        for (int r = 0; r < 8; r++)
#pragma unroll
            for (int c = 0; c < 8; c++)
                acc[r][c] += a[r] * b[c];
    }
#pragma unroll
    for (int r = 0; r < 8; r++)
#pragma unroll
        for (int c = 0; c < 8; c++)
            hp[(ty + 16 * r) * HP_STRIDE + tx + 16 * c] = acc[r][c];
    __syncthreads();   // hp + ssrc ready; xsT/W1s now dead -> AGG may be written

    // ---- Phase E: normalized aggregation + bias + relu -> AGG (= final h) ----
    {
        const float4 b1v = ((const float4*)b1)[lane];
        for (int d = warp * 16; d < warp * 16 + 16; d++) {
            float rd = rinv[d];
            float w0 = rd * rd;                 // self-loop norm
            float4 hv = ((const float4*)(hp + d * HP_STRIDE))[lane];
            float4 a4 = make_float4(hv.x * w0, hv.y * w0, hv.z * w0, hv.w * w0);
            int st = offs[d], en = st + cnt[d] - 1;
            for (int e = st; e < en; e++) {
                int s = ssrc[e];
                float w = rinv[s] * rd;
                float4 hs = ((const float4*)(hp + s * HP_STRIDE))[lane];
                a4.x += w * hs.x; a4.y += w * hs.y;
                a4.z += w * hs.z; a4.w += w * hs.w;
            }
            a4.x = fmaxf(a4.x + b1v.x, 0.f);
            a4.y = fmaxf(a4.y + b1v.y, 0.f);
            a4.z = fmaxf(a4.z + b1v.z, 0.f);
            a4.w = fmaxf(a4.w + b1v.w, 0.f);
            ((float4*)(AGG + d * HP_STRIDE))[lane] = a4;
        }
    }
    __syncthreads();

    // ---- Phase F: t[i] = h[i] . Ws   (score GEMV, pre-aggregation) ----
    {
        const float4 wsv = ((const float4*)Ws)[lane];
        for (int i = warp * 16; i < warp * 16 + 16; i++) {
            float4 hv = ((const float4*)(AGG + i * HP_STRIDE))[lane];
            float p = hv.x * wsv.x + hv.y * wsv.y + hv.z * wsv.z + hv.w * wsv.w;
#pragma unroll
            for (int o = 16; o; o >>= 1) p += __shfl_xor_sync(0xFFFFFFFFu, p, o);
            if (lane == 0) tval[i] = p;
        }
    }
    __syncthreads();

    // ---- score[d] = aggregate(t) + bs ----
    if (t < 128) {
        int d = t;
        float rd = rinv[d];
        float sc = rd * rd * tval[d];
        int st = offs[d], en = st + cnt[d] - 1;
        for (int e = st; e < en; e++) {
            int s = ssrc[e];
            sc += rd * rinv[s] * tval[s];
        }
        score[d] = sc + bs[0];
    }
    __syncthreads();

    // ---- top-K selection via rank (matches lax.top_k tie-break by index) ----
    if (t < 128) {
        float sd = score[t];
        int rank = 0;
        for (int j = 0; j < 128; j++) {
            float sj = score[j];
            rank += (sj > sd) || (sj == sd && j < t);
        }
        wsel[t] = (rank < KSEL) ? (tanhf(sd) * (1.0f / KSEL)) : 0.0f;
    }
    __syncthreads();

    // ---- pooled[f] = mean over kept nodes of h * tanh(score) ----
    if (t < 128) {
        float p = 0.f;
        for (int d = 0; d < 128; d++)
            p += wsel[d] * AGG[d * HP_STRIDE + t];
        pooled[t] = p;
    }
    __syncthreads();

    // ---- final linear: out[g] = pooled @ Wlin + blin ----
    if (t < 128) {
        float o = blin[t];
        for (int k = 0; k < 128; k++)
            o += pooled[k] * Wlin[k * 128 + t];
        out[(size_t)g * HID + t] = o;
    }
}

extern "C" void kernel_launch(void* const* d_in, const int* in_sizes, int n_in,
                              void* d_out, int out_size) {
    const float* x    = (const float*)d_in[0];
    const int*   ei   = (const int*)  d_in[1];
    // d_in[2] = batch (unused; structure is uniform)
    const float* W1   = (const float*)d_in[3];
    const float* b1   = (const float*)d_in[4];
    const float* Ws   = (const float*)d_in[5];
    const float* bs   = (const float*)d_in[6];
    const float* Wlin = (const float*)d_in[7];
    const float* blin = (const float*)d_in[8];
    float* out = (float*)d_out;

    const int E = in_sizes[1] / 2;            // 1,048,576
    const int* esrc = ei;
    const int* edst = ei + E;

    cudaFuncSetAttribute(sagpool_fused_kernel,
                         cudaFuncAttributeMaxDynamicSharedMemorySize, SMEM_BYTES);
    sagpool_fused_kernel<<<NB, 256, SMEM_BYTES>>>(
        x, esrc, edst, W1, b1, Ws, bs, Wlin, blin, out);
}

// round 2
// speedup vs baseline: 1.1665x; 1.1665x over previous
#include <cuda_runtime.h>
#include <math.h>

// Problem constants (fixed by dataset)
#define NB    512     // graphs
#define NPG   128     // nodes per graph
#define EPG   2048    // edges per graph
#define HID   128
#define KSEL  64

// ---- shared memory layout (floats) ----
// Region R0 (reused):
//   GEMM phase:  xsT half [64][129] (8256 floats) + W1 half [64][128] (8192) = 16448
//   after GEMM:  hp/AGG  [128][132] = 16896 floats
constexpr int XS_ST   = 129;
constexpr int HP_ST   = 132;
constexpr int SZ_R0   = HP_ST * 128;          // 16896
constexpr int OFF_W1H = 64 * XS_ST;           // 8256 (W1 half after xsT half)
constexpr int OFF_MISC = SZ_R0;
// misc: ssrc u16[2048] (1024 f) + wedge f32[2048] + cnt/offs/pos int[128]*3
//       + rinv/tval/score/wsel/pooled f32[128]*5
constexpr int MISC_FLOATS = 1024 + 2048 + 8 * 128;   // 4096
constexpr int SMEM_FLOATS = OFF_MISC + MISC_FLOATS;  // 20992
constexpr int SMEM_BYTES  = SMEM_FLOATS * 4;         // 83,968 B -> 2 CTAs/SM

extern __shared__ float S[];

__device__ __forceinline__ unsigned long long pack_dup(float a) {
    unsigned long long r;
    unsigned int ab = __float_as_uint(a);
    asm("mov.b64 %0, {%1, %1};" : "=l"(r) : "r"(ab));
    return r;
}
__device__ __forceinline__ void ffma2(unsigned long long& d,
                                      unsigned long long a,
                                      unsigned long long b) {
    asm("fma.rn.f32x2 %0, %1, %2, %0;" : "+l"(d) : "l"(a), "l"(b));
}

__global__ void __launch_bounds__(256, 2) sagpool_fused_kernel(
    const float* __restrict__ x,
    const int*   __restrict__ esrc,
    const int*   __restrict__ edst,
    const float* __restrict__ W1,
    const float* __restrict__ b1,
    const float* __restrict__ Ws,
    const float* __restrict__ bs,
    const float* __restrict__ Wlin,
    const float* __restrict__ blin,
    float*       __restrict__ out)
{
    const int g = blockIdx.x;
    const int t = threadIdx.x;
    const int lane = t & 31;
    const int warp = t >> 5;

    float* xsT = S;                          // [64][129] during GEMM halves
    float* W1h = S + OFF_W1H;                // [64][128] during GEMM halves
    float* hp  = S;                          // [128][132] after GEMM (= AGG later)
    unsigned short* ssrc = (unsigned short*)(S + OFF_MISC);   // 2048 u16
    float* wedge  = S + OFF_MISC + 1024;     // 2048 edge norm weights
    int*   cnt    = (int*)(wedge + 2048);
    int*   offs   = cnt  + 128;
    int*   pos    = offs + 128;
    float* rinv   = (float*)(pos + 128);
    float* tval   = rinv  + 128;
    float* score  = tval  + 128;
    float* wsel   = score + 128;
    float* pooled = wsel  + 128;

    // ---- Phase A: degree counting (self-loop included) ----
    if (t < 128) cnt[t] = 1;
    __syncthreads();

    const int ebase = g * EPG;
    int sloc[8], dloc[8];
#pragma unroll
    for (int e = 0; e < 8; e++) {
        int ei = ebase + t + e * 256;           // coalesced
        sloc[e] = esrc[ei] & (NPG - 1);
        dloc[e] = edst[ei] & (NPG - 1);
        atomicAdd(&cnt[dloc[e]], 1);
    }
    __syncthreads();

    // ---- rinv + exclusive prefix sum of incoming-edge counts ----
    if (t < 128) {
        rinv[t] = rsqrtf((float)cnt[t]);
        offs[t] = cnt[t] - 1;                  // incoming (non-self) count
    }
    __syncthreads();
    for (int sh = 1; sh < 128; sh <<= 1) {     // Hillis-Steele inclusive scan
        int v = 0;
        if (t < 128 && t >= sh) v = offs[t - sh];
        __syncthreads();
        if (t < 128) offs[t] += v;
        __syncthreads();
    }
    if (t < 128) pos[t] = offs[t] - (cnt[t] - 1);  // exclusive start
    __syncthreads();
    if (t < 128) offs[t] = pos[t];
    __syncthreads();

    // ---- counting-sort scatter: sources + precomputed norm weights per dst ----
#pragma unroll
    for (int e = 0; e < 8; e++) {
        int p = atomicAdd(&pos[dloc[e]], 1);
        ssrc[p]  = (unsigned short)sloc[e];
        wedge[p] = rinv[sloc[e]] * rinv[dloc[e]];
    }
    // readers sync inside GEMM phase below

    // ---- Phase C: GEMM hp = x_g @ W1 with K split in 2 halves, f32x2 FMA ----
    const int tx = t & 15, ty = t >> 4;
    // each thread: rows ty+16r (r<8), col pairs 2tx+32c (c<4)
    unsigned long long acc[8][4];
#pragma unroll
    for (int r = 0; r < 8; r++)
#pragma unroll
        for (int c = 0; c < 4; c++) acc[r][c] = 0ull;

    const float* xg = x + (size_t)g * NPG * HID;
#pragma unroll 1
    for (int h = 0; h < 2; h++) {
        // load x half transposed: xsT[kk][i] = x[i][64h+kk]
        for (int idx = t; idx < 64 * 128; idx += 256) {
            int i = idx >> 6, kk = idx & 63;
            xsT[kk * XS_ST + i] = xg[i * HID + h * 64 + kk];
        }
        // load W1 half: W1h[kk][j] = W1[64h+kk][j]
        for (int idx = t; idx < 64 * 128; idx += 256)
            W1h[idx] = W1[h * 64 * 128 + idx];
        __syncthreads();

#pragma unroll 2
        for (int kk = 0; kk < 64; kk++) {
            unsigned long long a2[8], b2[4];
#pragma unroll
            for (int r = 0; r < 8; r++)
                a2[r] = pack_dup(xsT[kk * XS_ST + ty + 16 * r]);
#pragma unroll
            for (int c = 0; c < 4; c++)
                b2[c] = *(const unsigned long long*)(W1h + kk * 128 + 2 * tx + 32 * c);
#pragma unroll
            for (int r = 0; r < 8; r++)
#pragma unroll
                for (int c = 0; c < 4; c++)
                    ffma2(acc[r][c], a2[r], b2[c]);
        }
        __syncthreads();   // protect tiles before next-half load / hp store
    }

    // store acc -> hp (same region as tiles, now dead)
#pragma unroll
    for (int r = 0; r < 8; r++)
#pragma unroll
        for (int c = 0; c < 4; c++)
            *(float2*)(hp + (ty + 16 * r) * HP_ST + 2 * tx + 32 * c) =
                *(float2*)&acc[r][c];
    __syncthreads();   // hp + ssrc/wedge ready

    // ---- Phase E: normalized aggregation -> registers (then overwrite hp) ----
    float4 rA[16];
    {
        const float4 b1v = ((const float4*)b1)[lane];
#pragma unroll 1
        for (int dd = 0; dd < 16; dd++) {
            int d = warp * 16 + dd;
            float rd = rinv[d];
            float w0 = rd * rd;                 // self-loop norm
            float4 hv = *(const float4*)(hp + d * HP_ST + 4 * lane);
            float4 a4 = make_float4(hv.x * w0, hv.y * w0, hv.z * w0, hv.w * w0);
            int st = offs[d], en = st + cnt[d] - 1;
            for (int e = st; e < en; e++) {
                int s = ssrc[e];
                float w = wedge[e];
                float4 hs = *(const float4*)(hp + s * HP_ST + 4 * lane);
                a4.x = fmaf(w, hs.x, a4.x); a4.y = fmaf(w, hs.y, a4.y);
                a4.z = fmaf(w, hs.z, a4.z); a4.w = fmaf(w, hs.w, a4.w);
            }
            a4.x = fmaxf(a4.x + b1v.x, 0.f);
            a4.y = fmaxf(a4.y + b1v.y, 0.f);
            a4.z = fmaxf(a4.z + b1v.z, 0.f);
            a4.w = fmaxf(a4.w + b1v.w, 0.f);
            rA[dd] = a4;
        }
    }
    __syncthreads();   // all hp reads done
    float* AGG = hp;   // overwrite in place
#pragma unroll
    for (int dd = 0; dd < 16; dd++)
        *(float4*)(AGG + (warp * 16 + dd) * HP_ST + 4 * lane) = rA[dd];
    __syncthreads();

    // ---- Phase F: tval[i] = h[i] . Ws  (pre-aggregation score GEMV) ----
    {
        const float4 wsv = ((const float4*)Ws)[lane];
        for (int i = warp * 16; i < warp * 16 + 16; i++) {
            float4 hv = *(const float4*)(AGG + i * HP_ST + 4 * lane);
            float p = hv.x * wsv.x + hv.y * wsv.y + hv.z * wsv.z + hv.w * wsv.w;
#pragma unroll
            for (int o = 16; o; o >>= 1) p += __shfl_xor_sync(0xFFFFFFFFu, p, o);
            if (lane == 0) tval[i] = p;
        }
    }
    __syncthreads();

    // ---- score[d] = aggregate(tval) + bs ----
    if (t < 128) {
        int d = t;
        float rd = rinv[d];
        float sc = rd * rd * tval[d];
        int st = offs[d], en = st + cnt[d] - 1;
        for (int e = st; e < en; e++)
            sc = fmaf(wedge[e], tval[ssrc[e]], sc);
        score[d] = sc + bs[0];
    }
    __syncthreads();

    // ---- top-K via rank (matches lax.top_k index tie-break) ----
    if (t < 128) {
        float sd = score[t];
        int rank = 0;
        for (int j = 0; j < 128; j++) {
            float sj = score[j];
            rank += (sj > sd) || (sj == sd && j < t);
        }
        wsel[t] = (rank < KSEL) ? (tanhf(sd) * (1.0f / KSEL)) : 0.0f;
    }
    __syncthreads();

    // ---- pooled[f] = sum_d wsel[d] * AGG[d][f] ----
    if (t < 128) {
        float p = 0.f;
        for (int d = 0; d < 128; d++)
            p = fmaf(wsel[d], AGG[d * HP_ST + t], p);
        pooled[t] = p;
    }
    __syncthreads();

    // ---- final linear: out[g] = pooled @ Wlin + blin ----
    if (t < 128) {
        float o = blin[t];
        for (int k = 0; k < 128; k++)
            o = fmaf(pooled[k], Wlin[k * 128 + t], o);
        out[(size_t)g * HID + t] = o;
    }
}

extern "C" void kernel_launch(void* const* d_in, const int* in_sizes, int n_in,
                              void* d_out, int out_size) {
    const float* x    = (const float*)d_in[0];
    const int*   ei   = (const int*)  d_in[1];
    // d_in[2] = batch (unused; structure is uniform)
    const float* W1   = (const float*)d_in[3];
    const float* b1   = (const float*)d_in[4];
    const float* Ws   = (const float*)d_in[5];
    const float* bs   = (const float*)d_in[6];
    const float* Wlin = (const float*)d_in[7];
    const float* blin = (const float*)d_in[8];
    float* out = (float*)d_out;

    const int E = in_sizes[1] / 2;            // 1,048,576
    const int* esrc = ei;
    const int* edst = ei + E;

    cudaFuncSetAttribute(sagpool_fused_kernel,
                         cudaFuncAttributeMaxDynamicSharedMemorySize, SMEM_BYTES);
    sagpool_fused_kernel<<<NB, 256, SMEM_BYTES>>>(
        x, esrc, edst, W1, b1, Ws, bs, Wlin, blin, out);
}

// round 6
// speedup vs baseline: 1.6194x; 1.3882x over previous
#include <cuda_runtime.h>
#include <cuda_bf16.h>
#include <cstdint>
#include <stdint.h>
#include <math.h>

// Problem constants (fixed by dataset)
#define NB    512
#define NPG   128
#define EPG   2048
#define HID   128
#define KSEL  64

// ---- smem layout (bytes) ----
// GEMM phase (per K-chunk of 64): 128 rows x 64 bf16, padded stride 144B
//   xs_hi [0,18432)  xs_lo [18432,36864)  W_hi [36864,55296)  W_lo [55296,73728)
// after GEMM: hp/AGG [128][132] fp32 = 67,584 B (overlaps tiles)
constexpr int ROW_B     = 144;                   // padded row stride (bytes) = 72 bf16
constexpr int HP_ST     = 132;
constexpr int OFF_MISC  = 18432;                 // floats (= 73,728 B)
constexpr int MISC_FLOATS = 4096;
constexpr int SMEM_FLOATS = OFF_MISC + MISC_FLOATS;   // 22528
constexpr int SMEM_BYTES  = SMEM_FLOATS * 4;          // 90,112 B -> 2 CTAs/SM

// W1^T hi|lo bf16, 256B rows (full K), written once per launch
__device__ __align__(16) unsigned char g_WT[65536];

__device__ __forceinline__ unsigned smem_u32(const void* p) {
    unsigned a;
    asm("{ .reg .u64 t; cvta.to.shared.u64 t, %1; cvt.u32.u64 %0, t; }" : "=r"(a) : "l"(p));
    return a;
}

#define LDSM4(r, addr) \
    asm volatile("ldmatrix.sync.aligned.m8n8.x4.shared.b16 {%0,%1,%2,%3}, [%4];" \
        : "=r"((r)[0]), "=r"((r)[1]), "=r"((r)[2]), "=r"((r)[3]) : "r"(addr))

#define MMA16816(c, a, b0, b1) \
    asm volatile("mma.sync.aligned.m16n8k16.row.col.f32.bf16.bf16.f32 " \
        "{%0,%1,%2,%3},{%4,%5,%6,%7},{%8,%9},{%0,%1,%2,%3};" \
        : "+f"((c)[0]), "+f"((c)[1]), "+f"((c)[2]), "+f"((c)[3]) \
        : "r"((a)[0]), "r"((a)[1]), "r"((a)[2]), "r"((a)[3]), "r"(b0), "r"(b1))

// ---------------- prep kernel: W1^T -> bf16 hi/lo, 256B rows ----------------
__global__ void prep_W_kernel(const float* __restrict__ W1) {
    int i = blockIdx.x * 256 + threadIdx.x;   // 16384 elements
    int k = i >> 7, n = i & 127;              // W1[k][n] -> WT[n][k]
    float v = W1[k * 128 + n];
    __nv_bfloat16 hi = __float2bfloat16(v);
    __nv_bfloat16 lo = __float2bfloat16(v - __bfloat162float(hi));
    unsigned off = (unsigned)n * 256u + (unsigned)k * 2u;
    *(__nv_bfloat16*)(g_WT + off)          = hi;
    *(__nv_bfloat16*)(g_WT + 32768u + off) = lo;
}

// ---------------- main fused kernel: one block per graph ----------------
extern __shared__ float S[];

__global__ void __launch_bounds__(256, 2) sagpool_fused_kernel(
    const float* __restrict__ x,
    const int*   __restrict__ esrc,
    const int*   __restrict__ edst,
    const float* __restrict__ b1,
    const float* __restrict__ Ws,
    const float* __restrict__ bs,
    const float* __restrict__ Wlin,
    const float* __restrict__ blin,
    float*       __restrict__ out)
{
    const int g = blockIdx.x;
    const int t = threadIdx.x;
    const int lane = t & 31;
    const int warp = t >> 5;

    float* hp = S;                                        // [128][132] after GEMM
    unsigned short* ssrc = (unsigned short*)(S + OFF_MISC);
    float* wedge  = S + OFF_MISC + 1024;
    int*   cnt    = (int*)(wedge + 2048);
    int*   offs   = cnt  + 128;
    int*   pos    = offs + 128;
    float* rinv   = (float*)(pos + 128);
    float* tval   = rinv  + 128;
    float* score  = tval  + 128;
    float* wsel   = score + 128;
    float* pooled = wsel  + 128;

    // ---- Phase A: degree counting ----
    if (t < 128) cnt[t] = 1;                  // self loop
    __syncthreads();

    const int ebase = g * EPG;
    int sloc[8], dloc[8];
#pragma unroll
    for (int e = 0; e < 8; e++) {
        int ei = ebase + t + e * 256;
        sloc[e] = esrc[ei] & (NPG - 1);
        dloc[e] = edst[ei] & (NPG - 1);
        atomicAdd(&cnt[dloc[e]], 1);
    }
    __syncthreads();

    // ---- Phase B: rinv + scan + counting-sort scatter ----
    if (t < 128) {
        rinv[t] = rsqrtf((float)cnt[t]);
        offs[t] = cnt[t] - 1;
    }
    __syncthreads();
    for (int sh = 1; sh < 128; sh <<= 1) {
        int v = 0;
        if (t < 128 && t >= sh) v = offs[t - sh];
        __syncthreads();
        if (t < 128) offs[t] += v;
        __syncthreads();
    }
    if (t < 128) pos[t] = offs[t] - (cnt[t] - 1);
    __syncthreads();
    if (t < 128) offs[t] = pos[t];
    __syncthreads();
#pragma unroll
    for (int e = 0; e < 8; e++) {
        int p = atomicAdd(&pos[dloc[e]], 1);
        ssrc[p]  = (unsigned short)sloc[e];
        wedge[p] = rinv[sloc[e]] * rinv[dloc[e]];
    }
    // (scatter consumers sync inside the GEMM below)

    // ---- Phase C: GEMM hp = x @ W1 via mma.sync bf16 3-term split, K in 2 chunks ----
    // warp tiling: 4 warps along M (32 rows), 2 along N (64 cols)
    const int m0 = (warp & 3) * 32;
    const int n0 = (warp >> 2) * 64;
    const unsigned q = (unsigned)lane >> 3, r8 = (unsigned)lane & 7;
    const unsigned SMB = smem_u32(S);

    // A (x tile): row = m0 + (q&1)*8 + r8, colByte = (q>>1)*16
    const unsigned aHi0 = SMB + (m0 + (q & 1) * 8 + r8) * ROW_B + (q >> 1) * 16;
    const unsigned aHi1 = aHi0 + 16 * ROW_B;
    const unsigned aLo0 = aHi0 + 18432u;
    const unsigned aLo1 = aHi1 + 18432u;
    // B (W1T tile): row = n0 + ((q>>1)&1)*8 + r8, colByte = (q&1)*16
    const unsigned bRow = (n0 + ((q >> 1) & 1) * 8 + r8) * ROW_B + (q & 1) * 16;
    const unsigned bHiB = SMB + 36864u + bRow;
    const unsigned bLoB = SMB + 55296u + bRow;

    float acc[2][8][4];
#pragma unroll
    for (int mt = 0; mt < 2; mt++)
#pragma unroll
        for (int nt = 0; nt < 8; nt++)
#pragma unroll
            for (int i = 0; i < 4; i++) acc[mt][nt][i] = 0.f;

    const float* xg = x + (size_t)g * NPG * HID;
    unsigned short* xs_hi = (unsigned short*)S;
    unsigned short* xs_lo = xs_hi + 9216;            // +18432 B

#pragma unroll 1
    for (int h = 0; h < 2; h++) {
        if (h) __syncthreads();                      // chunk-0 reads done before restage
        // stage x chunk: element (row, 64h+k), k<64
        for (int idx = t; idx < 128 * 64; idx += 256) {
            int row = idx >> 6, k = idx & 63;
            float v = xg[row * HID + h * 64 + k];
            __nv_bfloat16 hi = __float2bfloat16(v);
            __nv_bfloat16 lo = __float2bfloat16(v - __bfloat162float(hi));
            xs_hi[row * 72 + k] = __bfloat16_as_ushort(hi);
            xs_lo[row * 72 + k] = __bfloat16_as_ushort(lo);
        }
        // stage W chunk: g_WT rows are 256B; take 128B half h -> 144B padded rows
        {
            int4* wh = (int4*)((char*)S + 36864);
            int4* wl = (int4*)((char*)S + 55296);
            for (int i = t; i < 1024; i += 256) {
                int row = i >> 3, c = i & 7;          // 8 int4 per row
                wh[row * 9 + c] = *(const int4*)(g_WT + row * 256 + h * 128 + c * 16);
                wl[row * 9 + c] = *(const int4*)(g_WT + 32768 + row * 256 + h * 128 + c * 16);
            }
        }
        __syncthreads();

#pragma unroll
        for (int kk = 0; kk < 4; kk++) {              // 4 x K16 = 64
            const unsigned ko = (unsigned)kk * 32u;   // bytes
            unsigned ah0[4], ah1[4], al0[4], al1[4];
            LDSM4(ah0, aHi0 + ko);
            LDSM4(ah1, aHi1 + ko);
            LDSM4(al0, aLo0 + ko);
            LDSM4(al1, aLo1 + ko);
#pragma unroll
            for (int p = 0; p < 4; p++) {
                unsigned bh[4], bl[4];
                LDSM4(bh, bHiB + p * (16 * ROW_B) + ko);
                LDSM4(bl, bLoB + p * (16 * ROW_B) + ko);
                // hi*hi
                MMA16816(acc[0][2 * p],     ah0, bh[0], bh[1]);
                MMA16816(acc[0][2 * p + 1], ah0, bh[2], bh[3]);
                MMA16816(acc[1][2 * p],     ah1, bh[0], bh[1]);
                MMA16816(acc[1][2 * p + 1], ah1, bh[2], bh[3]);
                // lo*hi
                MMA16816(acc[0][2 * p],     al0, bh[0], bh[1]);
                MMA16816(acc[0][2 * p + 1], al0, bh[2], bh[3]);
                MMA16816(acc[1][2 * p],     al1, bh[0], bh[1]);
                MMA16816(acc[1][2 * p + 1], al1, bh[2], bh[3]);
                // hi*lo
                MMA16816(acc[0][2 * p],     ah0, bl[0], bl[1]);
                MMA16816(acc[0][2 * p + 1], ah0, bl[2], bl[3]);
                MMA16816(acc[1][2 * p],     ah1, bl[0], bl[1]);
                MMA16816(acc[1][2 * p + 1], ah1, bl[2], bl[3]);
            }
        }
    }
    __syncthreads();   // all tile reads done -> hp may overwrite region

    {
        const int rb = lane >> 2, cb = 2 * (lane & 3);
#pragma unroll
        for (int mt = 0; mt < 2; mt++)
#pragma unroll
            for (int nt = 0; nt < 8; nt++) {
                int row = m0 + 16 * mt + rb;
                int col = n0 + 8 * nt + cb;
                *(float2*)(hp + row * HP_ST + col) =
                    make_float2(acc[mt][nt][0], acc[mt][nt][1]);
                *(float2*)(hp + (row + 8) * HP_ST + col) =
                    make_float2(acc[mt][nt][2], acc[mt][nt][3]);
            }
    }
    __syncthreads();   // hp + ssrc/wedge ready

    // ---- Phase E: normalized aggregation + bias + relu (into registers) ----
    float4 rA[16];
    {
        const float4 b1v = ((const float4*)b1)[lane];
#pragma unroll 1
        for (int dd = 0; dd < 16; dd++) {
            int d = warp * 16 + dd;
            float rd = rinv[d];
            float w0 = rd * rd;
            float4 hv = *(const float4*)(hp + d * HP_ST + 4 * lane);
            float4 a4 = make_float4(hv.x * w0, hv.y * w0, hv.z * w0, hv.w * w0);
            int st = offs[d], en = st + cnt[d] - 1;
            for (int e = st; e < en; e++) {
                int s = ssrc[e];
                float w = wedge[e];
                float4 hs = *(const float4*)(hp + s * HP_ST + 4 * lane);
                a4.x = fmaf(w, hs.x, a4.x); a4.y = fmaf(w, hs.y, a4.y);
                a4.z = fmaf(w, hs.z, a4.z); a4.w = fmaf(w, hs.w, a4.w);
            }
            a4.x = fmaxf(a4.x + b1v.x, 0.f);
            a4.y = fmaxf(a4.y + b1v.y, 0.f);
            a4.z = fmaxf(a4.z + b1v.z, 0.f);
            a4.w = fmaxf(a4.w + b1v.w, 0.f);
            rA[dd] = a4;
        }
    }
    __syncthreads();
    float* AGG = hp;
#pragma unroll
    for (int dd = 0; dd < 16; dd++)
        *(float4*)(AGG + (warp * 16 + dd) * HP_ST + 4 * lane) = rA[dd];
    __syncthreads();

    // ---- Phase F: tval[i] = h[i] . Ws ----
    {
        const float4 wsv = ((const float4*)Ws)[lane];
        for (int i = warp * 16; i < warp * 16 + 16; i++) {
            float4 hv = *(const float4*)(AGG + i * HP_ST + 4 * lane);
            float p = hv.x * wsv.x + hv.y * wsv.y + hv.z * wsv.z + hv.w * wsv.w;
#pragma unroll
            for (int o = 16; o; o >>= 1) p += __shfl_xor_sync(0xFFFFFFFFu, p, o);
            if (lane == 0) tval[i] = p;
        }
    }
    __syncthreads();

    // ---- score[d] = aggregate(tval) + bs ----
    if (t < 128) {
        int d = t;
        float rd = rinv[d];
        float sc = rd * rd * tval[d];
        int st = offs[d], en = st + cnt[d] - 1;
        for (int e = st; e < en; e++)
            sc = fmaf(wedge[e], tval[ssrc[e]], sc);
        score[d] = sc + bs[0];
    }
    __syncthreads();

    // ---- top-K via rank (matches lax.top_k index tie-break) ----
    if (t < 128) {
        float sd = score[t];
        int rank = 0;
        for (int j = 0; j < 128; j++) {
            float sj = score[j];
            rank += (sj > sd) || (sj == sd && j < t);
        }
        wsel[t] = (rank < KSEL) ? (tanhf(sd) * (1.0f / KSEL)) : 0.0f;
    }
    __syncthreads();

    // ---- pooled[f] = sum_d wsel[d] * AGG[d][f] ----
    if (t < 128) {
        float p = 0.f;
        for (int d = 0; d < 128; d++)
            p = fmaf(wsel[d], AGG[d * HP_ST + t], p);
        pooled[t] = p;
    }
    __syncthreads();

    // ---- final linear ----
    if (t < 128) {
        float o = blin[t];
        for (int k = 0; k < 128; k++)
            o = fmaf(pooled[k], Wlin[k * 128 + t], o);
        out[(size_t)g * HID + t] = o;
    }
}

extern "C" void kernel_launch(void* const* d_in, const int* in_sizes, int n_in,
                              void* d_out, int out_size) {
    const float* x    = (const float*)d_in[0];
    const int*   ei   = (const int*)  d_in[1];
    // d_in[2] = batch (unused)
    const float* W1   = (const float*)d_in[3];
    const float* b1   = (const float*)d_in[4];
    const float* Ws   = (const float*)d_in[5];
    const float* bs   = (const float*)d_in[6];
    const float* Wlin = (const float*)d_in[7];
    const float* blin = (const float*)d_in[8];
    float* out = (float*)d_out;

    const int E = in_sizes[1] / 2;
    const int* esrc = ei;
    const int* edst = ei + E;

    prep_W_kernel<<<64, 256>>>(W1);

    cudaFuncSetAttribute(sagpool_fused_kernel,
                         cudaFuncAttributeMaxDynamicSharedMemorySize, SMEM_BYTES);
    sagpool_fused_kernel<<<NB, 256, SMEM_BYTES>>>(
        x, esrc, edst, b1, Ws, bs, Wlin, blin, out);
}

// round 8
// speedup vs baseline: 2.0878x; 1.2893x over previous
#include <cuda_runtime.h>
#include <cuda_fp16.h>
#include <cstdint>
#include <stdint.h>
#include <math.h>

#define NB    512
#define NPG   128
#define EPG   2048
#define HID   128
#define KSEL  64

// ---- smem byte map ----
// GEMM1 tiles (transient): xs_hi@0 xs_lo@18432 W_hi@36864 W_lo@55296 (end 73728)
// B tiles (hp'^T fp16):    BHI@0 (34816), BLO@34816 (end 69632), 272B rows
// AGG fp32 [128][132]:     @0 (67584) after GEMM2
// counts u8 [128][128]:    CNT8@69632 (16384)
// A tile (counts fp16):    ATILE@86016 (18432), 144B rows
// misc:                    @104448 (4096)
constexpr int BHI   = 0;
constexpr int BLO   = 34816;
constexpr int CNT8  = 69632;
constexpr int ATILE = 86016;
constexpr int MISCB = 104448;
constexpr int HP_ST = 132;
constexpr int SMEM_BYTES = 108544;               // 2 CTAs/SM

// W1^T hi|lo fp16, 256B rows (full K), written once per launch
__device__ __align__(16) unsigned char g_WT[65536];

__device__ __forceinline__ unsigned smem_u32(const void* p) {
    unsigned a;
    asm("{ .reg .u64 t; cvta.to.shared.u64 t, %1; cvt.u32.u64 %0, t; }" : "=r"(a) : "l"(p));
    return a;
}

#define LDSM4(r, addr) \
    asm volatile("ldmatrix.sync.aligned.m8n8.x4.shared.b16 {%0,%1,%2,%3}, [%4];" \
        : "=r"((r)[0]), "=r"((r)[1]), "=r"((r)[2]), "=r"((r)[3]) : "r"(addr))

#define MMA16816(c, a, b0, b1) \
    asm volatile("mma.sync.aligned.m16n8k16.row.col.f32.f16.f16.f32 " \
        "{%0,%1,%2,%3},{%4,%5,%6,%7},{%8,%9},{%0,%1,%2,%3};" \
        : "+f"((c)[0]), "+f"((c)[1]), "+f"((c)[2]), "+f"((c)[3]) \
        : "r"((a)[0]), "r"((a)[1]), "r"((a)[2]), "r"((a)[3]), "r"(b0), "r"(b1))

// ---------------- prep: W1^T -> fp16 hi/lo, 256B rows ----------------
__global__ void prep_W_kernel(const float* __restrict__ W1) {
    int i = blockIdx.x * 256 + threadIdx.x;
    int k = i >> 7, n = i & 127;              // W1[k][n] -> WT[n][k]
    float v = W1[k * 128 + n];
    __half hi = __float2half_rn(v);
    __half lo = __float2half_rn(v - __half2float(hi));
    unsigned off = (unsigned)n * 256u + (unsigned)k * 2u;
    *(__half*)(g_WT + off)          = hi;
    *(__half*)(g_WT + 32768u + off) = lo;
}

// ---------------- main fused kernel ----------------
extern __shared__ float S[];

__global__ void __launch_bounds__(256, 2) sagpool_fused_kernel(
    const float* __restrict__ x,
    const int*   __restrict__ esrc,
    const int*   __restrict__ edst,
    const float* __restrict__ b1,
    const float* __restrict__ Ws,
    const float* __restrict__ bs,
    const float* __restrict__ Wlin,
    const float* __restrict__ blin,
    float*       __restrict__ out)
{
    const int g = blockIdx.x;
    const int t = threadIdx.x;
    const int lane = t & 31;
    const int warp = t >> 5;

    char*  Sb     = (char*)S;
    float* AGG    = S;                                   // [128][132] after GEMM2
    int*   cntdeg = (int*)(Sb + MISCB);
    float* rinv   = (float*)(cntdeg + 128);
    float* b1s    = rinv  + 128;
    float* tval   = b1s   + 128;
    float* uvec   = tval  + 128;
    float* score  = uvec  + 128;
    float* wsel   = score + 128;
    float* pooled = wsel  + 128;

    // ---- Phase A: degree histogram + stage b1 ----
    if (t < 128) { cntdeg[t] = 1; b1s[t] = b1[t]; }
    __syncthreads();
    const int ebase = g * EPG;
#pragma unroll
    for (int e = 0; e < 8; e++)
        atomicAdd(&cntdeg[edst[ebase + t + e * 256] & (NPG - 1)], 1);
    __syncthreads();
    if (t < 128) rinv[t] = rsqrtf((float)cntdeg[t]);
    __syncthreads();

    // ---- Phase B: GEMM1 hp = x@W1 (fp16 3-term split, K in 2 chunks) ----
    const int m0 = (warp & 3) * 32;
    const int n0 = (warp >> 2) * 64;
    const unsigned q = (unsigned)lane >> 3, r8 = (unsigned)lane & 7;
    const unsigned SMB = smem_u32(S);

    const unsigned aHi0 = SMB + (m0 + (q & 1) * 8 + r8) * 144 + (q >> 1) * 16;
    const unsigned aHi1 = aHi0 + 16 * 144;
    const unsigned aLo0 = aHi0 + 18432u;
    const unsigned aLo1 = aHi1 + 18432u;
    const unsigned bRow = (n0 + ((q >> 1) & 1) * 8 + r8) * 144 + (q & 1) * 16;
    const unsigned bHiB = SMB + 36864u + bRow;
    const unsigned bLoB = SMB + 55296u + bRow;

    float acc[2][8][4];
#pragma unroll
    for (int mt = 0; mt < 2; mt++)
#pragma unroll
        for (int nt = 0; nt < 8; nt++)
#pragma unroll
            for (int i = 0; i < 4; i++) acc[mt][nt][i] = 0.f;

    const float* xg = x + (size_t)g * NPG * HID;
    unsigned short* xs_hi = (unsigned short*)S;
    unsigned short* xs_lo = xs_hi + 9216;

#pragma unroll 1
    for (int h = 0; h < 2; h++) {
        if (h) __syncthreads();
        for (int idx = t; idx < 128 * 64; idx += 256) {
            int row = idx >> 6, k = idx & 63;
            float v = xg[row * HID + h * 64 + k];
            __half hi = __float2half_rn(v);
            __half lo = __float2half_rn(v - __half2float(hi));
            xs_hi[row * 72 + k] = __half_as_ushort(hi);
            xs_lo[row * 72 + k] = __half_as_ushort(lo);
        }
        {
            int4* wh = (int4*)(Sb + 36864);
            int4* wl = (int4*)(Sb + 55296);
            for (int i = t; i < 1024; i += 256) {
                int row = i >> 3, c = i & 7;
                wh[row * 9 + c] = *(const int4*)(g_WT + row * 256 + h * 128 + c * 16);
                wl[row * 9 + c] = *(const int4*)(g_WT + 32768 + row * 256 + h * 128 + c * 16);
            }
        }
        __syncthreads();
#pragma unroll
        for (int kk = 0; kk < 4; kk++) {
            const unsigned ko = (unsigned)kk * 32u;
            unsigned ah0[4], ah1[4], al0[4], al1[4];
            LDSM4(ah0, aHi0 + ko);
            LDSM4(ah1, aHi1 + ko);
            LDSM4(al0, aLo0 + ko);
            LDSM4(al1, aLo1 + ko);
#pragma unroll
            for (int p = 0; p < 4; p++) {
                unsigned bh[4], bl[4];
                LDSM4(bh, bHiB + p * (16 * 144) + ko);
                LDSM4(bl, bLoB + p * (16 * 144) + ko);
                MMA16816(acc[0][2 * p],     ah0, bh[0], bh[1]);
                MMA16816(acc[0][2 * p + 1], ah0, bh[2], bh[3]);
                MMA16816(acc[1][2 * p],     ah1, bh[0], bh[1]);
                MMA16816(acc[1][2 * p + 1], ah1, bh[2], bh[3]);
                MMA16816(acc[0][2 * p],     al0, bh[0], bh[1]);
                MMA16816(acc[0][2 * p + 1], al0, bh[2], bh[3]);
                MMA16816(acc[1][2 * p],     al1, bh[0], bh[1]);
                MMA16816(acc[1][2 * p + 1], al1, bh[2], bh[3]);
                MMA16816(acc[0][2 * p],     ah0, bl[0], bl[1]);
                MMA16816(acc[0][2 * p + 1], ah0, bl[2], bl[3]);
                MMA16816(acc[1][2 * p],     ah1, bl[0], bl[1]);
                MMA16816(acc[1][2 * p + 1], ah1, bl[2], bl[3]);
            }
        }
    }
    __syncthreads();   // GEMM1 tile reads done

    // ---- Phase C: hp' = rinv[s]*hp -> transposed fp16 hi/lo B tiles; zero counts ----
    {
        const int rb = lane >> 2, cb = 2 * (lane & 3);
#pragma unroll
        for (int mt = 0; mt < 2; mt++) {
            int row0 = m0 + 16 * mt + rb;
            float rv0 = rinv[row0], rv1 = rinv[row0 + 8];
#pragma unroll
            for (int nt = 0; nt < 8; nt++) {
                int col = n0 + 8 * nt + cb;
#pragma unroll
                for (int i = 0; i < 4; i++) {
                    int row = (i >= 2) ? row0 + 8 : row0;
                    float rv = (i >= 2) ? rv1 : rv0;
                    int c = col + (i & 1);
                    float vv = acc[mt][nt][i] * rv;
                    __half hi = __float2half_rn(vv);
                    __half lo = __float2half_rn(vv - __half2float(hi));
                    *(__half*)(Sb + BHI + c * 272 + row * 2) = hi;
                    *(__half*)(Sb + BLO + c * 272 + row * 2) = lo;
                }
            }
        }
        int4 z = make_int4(0, 0, 0, 0);
        int4* cz = (int4*)(Sb + CNT8);
        for (int i = t; i < 1024; i += 256) cz[i] = z;
    }
    __syncthreads();

    // ---- Phase D: scatter edge counts into packed u8 matrix ----
    {
        int* cw = (int*)(Sb + CNT8);
#pragma unroll
        for (int e = 0; e < 8; e++) {
            int ei = ebase + t + e * 256;
            int s = esrc[ei] & (NPG - 1);
            int d = edst[ei] & (NPG - 1);
            atomicAdd(&cw[d * 32 + (s >> 2)], 1 << ((s & 3) * 8));
        }
    }
    __syncthreads();

    // ---- Phase E: GEMM2 h_agg_pre = N @ hp' (fp16 2-term), K(s) in 2 chunks ----
    const unsigned aA0 = SMB + (unsigned)ATILE + (m0 + (q & 1) * 8 + r8) * 144 + (q >> 1) * 16;
    const unsigned aA1 = aA0 + 16 * 144;
    const unsigned bRow2 = (n0 + ((q >> 1) & 1) * 8 + r8) * 272 + (q & 1) * 16;
    const unsigned bH2 = SMB + (unsigned)BHI + bRow2;
    const unsigned bL2 = SMB + (unsigned)BLO + bRow2;

    float acc2[2][8][4];
#pragma unroll
    for (int mt = 0; mt < 2; mt++)
#pragma unroll
        for (int nt = 0; nt < 8; nt++)
#pragma unroll
            for (int i = 0; i < 4; i++) acc2[mt][nt][i] = 0.f;

#pragma unroll 1
    for (int h = 0; h < 2; h++) {
        if (h) __syncthreads();
        // stage A tile: counts (+ self-loop) -> fp16 exact, [128 d][64 s], 144B rows
        {
            const int* cw = (const int*)(Sb + CNT8);
            for (int w = t; w < 128 * 16; w += 256) {
                int d = w >> 4, wi = w & 15;
                int word = cw[d * 32 + h * 16 + wi];
                int s0 = h * 64 + wi * 4;
                float f0 = (float)(word & 255)         + ((d == s0)     ? 1.f : 0.f);
                float f1 = (float)((word >> 8) & 255)  + ((d == s0 + 1) ? 1.f : 0.f);
                float f2 = (float)((word >> 16) & 255) + ((d == s0 + 2) ? 1.f : 0.f);
                float f3 = (float)((word >> 24) & 255) + ((d == s0 + 3) ? 1.f : 0.f);
                unsigned p0, p1;
                asm("cvt.rn.f16x2.f32 %0, %1, %2;" : "=r"(p0) : "f"(f1), "f"(f0));
                asm("cvt.rn.f16x2.f32 %0, %1, %2;" : "=r"(p1) : "f"(f3), "f"(f2));
                *(uint2*)(Sb + ATILE + d * 144 + wi * 8) = make_uint2(p0, p1);
            }
        }
        __syncthreads();
#pragma unroll
        for (int kk = 0; kk < 4; kk++) {
            const unsigned ko = (unsigned)kk * 32u;
            const unsigned bko = (unsigned)(h * 128) + ko;
            unsigned a0[4], a1[4];
            LDSM4(a0, aA0 + ko);
            LDSM4(a1, aA1 + ko);
#pragma unroll
            for (int p = 0; p < 4; p++) {
                unsigned bh[4], bl[4];
                LDSM4(bh, bH2 + p * (16 * 272) + bko);
                LDSM4(bl, bL2 + p * (16 * 272) + bko);
                MMA16816(acc2[0][2 * p],     a0, bh[0], bh[1]);
                MMA16816(acc2[0][2 * p + 1], a0, bh[2], bh[3]);
                MMA16816(acc2[1][2 * p],     a1, bh[0], bh[1]);
                MMA16816(acc2[1][2 * p + 1], a1, bh[2], bh[3]);
                MMA16816(acc2[0][2 * p],     a0, bl[0], bl[1]);
                MMA16816(acc2[0][2 * p + 1], a0, bl[2], bl[3]);
                MMA16816(acc2[1][2 * p],     a1, bl[0], bl[1]);
                MMA16816(acc2[1][2 * p + 1], a1, bl[2], bl[3]);
            }
        }
    }
    __syncthreads();   // GEMM2 reads done -> B tiles dead, AGG may be written

    // ---- Phase F: epilogue AGG = relu(rinv[d]*D + b1) ----
    {
        const int rb = lane >> 2, cb = 2 * (lane & 3);
#pragma unroll
        for (int mt = 0; mt < 2; mt++) {
            int row0 = m0 + 16 * mt + rb;
            float rv0 = rinv[row0], rv1 = rinv[row0 + 8];
#pragma unroll
            for (int nt = 0; nt < 8; nt++) {
                int col = n0 + 8 * nt + cb;
                float bb0 = b1s[col], bb1 = b1s[col + 1];
                float v0 = fmaxf(fmaf(rv0, acc2[mt][nt][0], bb0), 0.f);
                float v1 = fmaxf(fmaf(rv0, acc2[mt][nt][1], bb1), 0.f);
                float v2 = fmaxf(fmaf(rv1, acc2[mt][nt][2], bb0), 0.f);
                float v3 = fmaxf(fmaf(rv1, acc2[mt][nt][3], bb1), 0.f);
                *(float2*)(AGG + row0 * HP_ST + col)       = make_float2(v0, v1);
                *(float2*)(AGG + (row0 + 8) * HP_ST + col) = make_float2(v2, v3);
            }
        }
    }
    __syncthreads();

    // ---- Phase G: tval[i] = h[i] . Ws ----
    {
        const float4 wsv = ((const float4*)Ws)[lane];
        for (int i = warp * 16; i < warp * 16 + 16; i++) {
            float4 hv = *(const float4*)(AGG + i * HP_ST + 4 * lane);
            float p = hv.x * wsv.x + hv.y * wsv.y + hv.z * wsv.z + hv.w * wsv.w;
#pragma unroll
            for (int o = 16; o; o >>= 1) p += __shfl_xor_sync(0xFFFFFFFFu, p, o);
            if (lane == 0) tval[i] = p;
        }
    }
    __syncthreads();
    if (t < 128) uvec[t] = rinv[t] * tval[t];
    __syncthreads();

    // ---- Phase H: score[d] via dense u8 row sweep (bank-rotated) ----
    if (t < 128) {
        float rd = rinv[t];
        const int* cw = (const int*)(Sb + CNT8);
        float a = 0.f;
#pragma unroll 4
        for (int w0 = 0; w0 < 32; w0++) {
            int w = (w0 + lane) & 31;
            int word = cw[t * 32 + w];
            if (word) {
                int s0 = w * 4;
                a = fmaf((float)(word & 255),         uvec[s0],     a);
                a = fmaf((float)((word >> 8) & 255),  uvec[s0 + 1], a);
                a = fmaf((float)((word >> 16) & 255), uvec[s0 + 2], a);
                a = fmaf((float)((word >> 24) & 255), uvec[s0 + 3], a);
            }
        }
        score[t] = rd * rd * tval[t] + rd * a + bs[0];
    }
    __syncthreads();

    // ---- Phase I: top-K via rank (lax.top_k tie-break) ----
    if (t < 128) {
        float sd = score[t];
        int rank = 0;
        for (int j = 0; j < 128; j++) {
            float sj = score[j];
            rank += (sj > sd) || (sj == sd && j < t);
        }
        wsel[t] = (rank < KSEL) ? (tanhf(sd) * (1.0f / KSEL)) : 0.0f;
    }
    __syncthreads();

    // ---- Phase J: pooled[f] = sum_d wsel[d] * AGG[d][f] ----
    if (t < 128) {
        float p = 0.f;
        for (int d = 0; d < 128; d++)
            p = fmaf(wsel[d], AGG[d * HP_ST + t], p);
        pooled[t] = p;
    }
    __syncthreads();

    // ---- Phase K: final linear ----
    if (t < 128) {
        float o = blin[t];
        for (int k = 0; k < 128; k++)
            o = fmaf(pooled[k], Wlin[k * 128 + t], o);
        out[(size_t)g * HID + t] = o;
    }
}

extern "C" void kernel_launch(void* const* d_in, const int* in_sizes, int n_in,
                              void* d_out, int out_size) {
    const float* x    = (const float*)d_in[0];
    const int*   ei   = (const int*)  d_in[1];
    const float* W1   = (const float*)d_in[3];
    const float* b1   = (const float*)d_in[4];
    const float* Ws   = (const float*)d_in[5];
    const float* bs   = (const float*)d_in[6];
    const float* Wlin = (const float*)d_in[7];
    const float* blin = (const float*)d_in[8];
    float* out = (float*)d_out;

    const int E = in_sizes[1] / 2;
    const int* esrc = ei;
    const int* edst = ei + E;

    prep_W_kernel<<<64, 256>>>(W1);

    cudaFuncSetAttribute(sagpool_fused_kernel,
                         cudaFuncAttributeMaxDynamicSharedMemorySize, SMEM_BYTES);
    sagpool_fused_kernel<<<NB, 256, SMEM_BYTES>>>(
        x, esrc, edst, b1, Ws, bs, Wlin, blin, out);
}

// round 9
// speedup vs baseline: 2.1603x; 1.0347x over previous
#include <cuda_runtime.h>
#include <cuda_fp16.h>
#include <cstdint>
#include <stdint.h>
#include <math.h>

#define NB    512
#define NPG   128
#define EPG   2048
#define HID   128
#define KSEL  64

// ---- smem byte map ----
// GEMM1 tiles (transient): xs_hi@0 xs_lo@18432 W_hi@36864 W_lo@55296 (end 73728)
// B tiles hp' node-major [s][f] fp16, 272B rows: BHI@0 (34816), BLO@34816 (end 69632)
// AGG fp32 [128][132] @0 (67584) after GEMM2
// counts u8 [128][128]: CNT8@73728 (16384)  -- disjoint from GEMM1 tiles
// A tile (counts fp16): ATILE@90112 (18432), 144B rows
// misc @108544
constexpr int BHI   = 0;
constexpr int BLO   = 34816;
constexpr int CNT8  = 73728;
constexpr int ATILE = 90112;
constexpr int MISCB = 108544;
constexpr int HP_ST = 132;
constexpr int SMEM_BYTES = 113664;               // 2 CTAs/SM (227,328 <= 228KB)

// W1^T hi|lo fp16, 256B rows (full K), written once per launch
__device__ __align__(16) unsigned char g_WT[65536];

__device__ __forceinline__ unsigned smem_u32(const void* p) {
    unsigned a;
    asm("{ .reg .u64 t; cvta.to.shared.u64 t, %1; cvt.u32.u64 %0, t; }" : "=r"(a) : "l"(p));
    return a;
}

#define LDSM4(r, addr) \
    asm volatile("ldmatrix.sync.aligned.m8n8.x4.shared.b16 {%0,%1,%2,%3}, [%4];" \
        : "=r"((r)[0]), "=r"((r)[1]), "=r"((r)[2]), "=r"((r)[3]) : "r"(addr))

#define LDSM4T(r, addr) \
    asm volatile("ldmatrix.sync.aligned.m8n8.x4.trans.shared.b16 {%0,%1,%2,%3}, [%4];" \
        : "=r"((r)[0]), "=r"((r)[1]), "=r"((r)[2]), "=r"((r)[3]) : "r"(addr))

#define MMA16816(c, a, b0, b1) \
    asm volatile("mma.sync.aligned.m16n8k16.row.col.f32.f16.f16.f32 " \
        "{%0,%1,%2,%3},{%4,%5,%6,%7},{%8,%9},{%0,%1,%2,%3};" \
        : "+f"((c)[0]), "+f"((c)[1]), "+f"((c)[2]), "+f"((c)[3]) \
        : "r"((a)[0]), "r"((a)[1]), "r"((a)[2]), "r"((a)[3]), "r"(b0), "r"(b1))

// pack {upper=hi_, lower=lo} into u32 as f16x2
__device__ __forceinline__ unsigned pack_h2(float lo, float hi_) {
    unsigned r;
    asm("cvt.rn.f16x2.f32 %0, %1, %2;" : "=r"(r) : "f"(hi_), "f"(lo));
    return r;
}

// ---------------- prep: W1^T -> fp16 hi/lo, 256B rows ----------------
__global__ void prep_W_kernel(const float* __restrict__ W1) {
    int i = blockIdx.x * 256 + threadIdx.x;
    int k = i >> 7, n = i & 127;              // W1[k][n] -> WT[n][k]
    float v = W1[k * 128 + n];
    __half hi = __float2half_rn(v);
    __half lo = __float2half_rn(v - __half2float(hi));
    unsigned off = (unsigned)n * 256u + (unsigned)k * 2u;
    *(__half*)(g_WT + off)          = hi;
    *(__half*)(g_WT + 32768u + off) = lo;
}

// ---------------- main fused kernel ----------------
extern __shared__ float S[];

__global__ void __launch_bounds__(256, 2) sagpool_fused_kernel(
    const float* __restrict__ x,
    const int*   __restrict__ esrc,
    const int*   __restrict__ edst,
    const float* __restrict__ b1,
    const float* __restrict__ Ws,
    const float* __restrict__ bs,
    const float* __restrict__ Wlin,
    const float* __restrict__ blin,
    float*       __restrict__ out)
{
    const int g = blockIdx.x;
    const int t = threadIdx.x;
    const int lane = t & 31;
    const int warp = t >> 5;

    char*  Sb     = (char*)S;
    float* AGG    = S;                                   // [128][132] after GEMM2
    float* rinv   = (float*)(Sb + MISCB);
    float* b1s    = rinv  + 128;
    float* wss    = b1s   + 128;
    float* tval   = wss   + 128;
    float* uvec   = tval  + 128;
    float* score  = uvec  + 128;
    float* wsel   = score + 128;
    float* pooled = wsel  + 128;
    float* part   = pooled + 128;                        // 256 floats

    // ---- Phase A: zero CNT8, stage b1/Ws, single-pass edge scatter ----
    {
        int4 z = make_int4(0, 0, 0, 0);
        int4* cz = (int4*)(Sb + CNT8);
        for (int i = t; i < 1024; i += 256) cz[i] = z;
        if (t < 128) { b1s[t] = b1[t]; wss[t] = Ws[t]; }
    }
    __syncthreads();
    const int ebase = g * EPG;
    {
        int sl[8], dl[8];
#pragma unroll
        for (int e = 0; e < 8; e++) {
            int ei = ebase + t + e * 256;
            sl[e] = esrc[ei] & (NPG - 1);
            dl[e] = edst[ei] & (NPG - 1);
        }
        int* cw = (int*)(Sb + CNT8);
#pragma unroll
        for (int e = 0; e < 8; e++)
            atomicAdd(&cw[dl[e] * 32 + (sl[e] >> 2)], 1 << ((sl[e] & 3) * 8));
    }
    __syncthreads();
    if (t < 128) {      // degree from CNT8 row sum (+1 self loop)
        const int* cw = (const int*)(Sb + CNT8);
        int deg = 1;
#pragma unroll
        for (int w = 0; w < 32; w++) deg = __dp4a(cw[t * 32 + w], 0x01010101, deg);
        rinv[t] = rsqrtf((float)deg);
    }
    // (rinv consumers sync via GEMM1's internal barriers)

    // ---- Phase B: GEMM1 hp = x@W1 (fp16 3-term split, K in 2 chunks) ----
    const int m0 = (warp & 3) * 32;
    const int n0 = (warp >> 2) * 64;
    const unsigned q = (unsigned)lane >> 3, r8 = (unsigned)lane & 7;
    const unsigned SMB = smem_u32(S);

    const unsigned aHi0 = SMB + (m0 + (q & 1) * 8 + r8) * 144 + (q >> 1) * 16;
    const unsigned aHi1 = aHi0 + 16 * 144;
    const unsigned aLo0 = aHi0 + 18432u;
    const unsigned aLo1 = aHi1 + 18432u;
    const unsigned bRow = (n0 + ((q >> 1) & 1) * 8 + r8) * 144 + (q & 1) * 16;
    const unsigned bHiB = SMB + 36864u + bRow;
    const unsigned bLoB = SMB + 55296u + bRow;

    float acc[2][8][4];
#pragma unroll
    for (int mt = 0; mt < 2; mt++)
#pragma unroll
        for (int nt = 0; nt < 8; nt++)
#pragma unroll
            for (int i = 0; i < 4; i++) acc[mt][nt][i] = 0.f;

    const float* xg = x + (size_t)g * NPG * HID;
    unsigned* xs_hi32 = (unsigned*)S;                // 36 words/row (144B)
    unsigned* xs_lo32 = xs_hi32 + 4608;              // +18432B

#pragma unroll 1
    for (int h = 0; h < 2; h++) {
        if (h) __syncthreads();
        // stage x chunk as half2 pairs (16 iters/thread)
        for (int idx = t; idx < 128 * 32; idx += 256) {
            int row = idx >> 5, kp = idx & 31;
            float2 v = *(const float2*)(xg + row * HID + h * 64 + kp * 2);
            __half h0 = __float2half_rn(v.x);
            __half h1 = __float2half_rn(v.y);
            xs_hi32[row * 36 + kp] =
                ((unsigned)__half_as_ushort(h1) << 16) | (unsigned)__half_as_ushort(h0);
            xs_lo32[row * 36 + kp] =
                pack_h2(v.x - __half2float(h0), v.y - __half2float(h1));
        }
        {
            int4* wh = (int4*)(Sb + 36864);
            int4* wl = (int4*)(Sb + 55296);
            for (int i = t; i < 1024; i += 256) {
                int row = i >> 3, c = i & 7;
                wh[row * 9 + c] = *(const int4*)(g_WT + row * 256 + h * 128 + c * 16);
                wl[row * 9 + c] = *(const int4*)(g_WT + 32768 + row * 256 + h * 128 + c * 16);
            }
        }
        __syncthreads();
#pragma unroll
        for (int kk = 0; kk < 4; kk++) {
            const unsigned ko = (unsigned)kk * 32u;
            unsigned ah0[4], ah1[4], al0[4], al1[4];
            LDSM4(ah0, aHi0 + ko);
            LDSM4(ah1, aHi1 + ko);
            LDSM4(al0, aLo0 + ko);
            LDSM4(al1, aLo1 + ko);
#pragma unroll
            for (int p = 0; p < 4; p++) {
                unsigned bh[4], bl[4];
                LDSM4(bh, bHiB + p * (16 * 144) + ko);
                LDSM4(bl, bLoB + p * (16 * 144) + ko);
                MMA16816(acc[0][2 * p],     ah0, bh[0], bh[1]);
                MMA16816(acc[0][2 * p + 1], ah0, bh[2], bh[3]);
                MMA16816(acc[1][2 * p],     ah1, bh[0], bh[1]);
                MMA16816(acc[1][2 * p + 1], ah1, bh[2], bh[3]);
                MMA16816(acc[0][2 * p],     al0, bh[0], bh[1]);
                MMA16816(acc[0][2 * p + 1], al0, bh[2], bh[3]);
                MMA16816(acc[1][2 * p],     al1, bh[0], bh[1]);
                MMA16816(acc[1][2 * p + 1], al1, bh[2], bh[3]);
                MMA16816(acc[0][2 * p],     ah0, bl[0], bl[1]);
                MMA16816(acc[0][2 * p + 1], ah0, bl[2], bl[3]);
                MMA16816(acc[1][2 * p],     ah1, bl[0], bl[1]);
                MMA16816(acc[1][2 * p + 1], ah1, bl[2], bl[3]);
            }
        }
    }
    __syncthreads();   // GEMM1 tile reads done

    // ---- Phase C: hp' = rinv[s]*hp -> node-major [s][f] fp16 hi/lo (half2 stores) ----
    {
        const int rb = lane >> 2, cb = 2 * (lane & 3);
#pragma unroll
        for (int mt = 0; mt < 2; mt++) {
            int row0 = m0 + 16 * mt + rb;
            float rv0 = rinv[row0], rv1 = rinv[row0 + 8];
#pragma unroll
            for (int nt = 0; nt < 8; nt++) {
                int col = n0 + 8 * nt + cb;
                float v0 = acc[mt][nt][0] * rv0, v1 = acc[mt][nt][1] * rv0;
                float v2 = acc[mt][nt][2] * rv1, v3 = acc[mt][nt][3] * rv1;
                __half h0 = __float2half_rn(v0), h1 = __float2half_rn(v1);
                __half h2 = __float2half_rn(v2), h3 = __float2half_rn(v3);
                unsigned o0 = row0 * 272u + col * 2u;
                unsigned o1 = (row0 + 8) * 272u + col * 2u;
                *(unsigned*)(Sb + BHI + o0) =
                    ((unsigned)__half_as_ushort(h1) << 16) | (unsigned)__half_as_ushort(h0);
                *(unsigned*)(Sb + BHI + o1) =
                    ((unsigned)__half_as_ushort(h3) << 16) | (unsigned)__half_as_ushort(h2);
                *(unsigned*)(Sb + BLO + o0) =
                    pack_h2(v0 - __half2float(h0), v1 - __half2float(h1));
                *(unsigned*)(Sb + BLO + o1) =
                    pack_h2(v2 - __half2float(h2), v3 - __half2float(h3));
            }
        }
    }
    __syncthreads();

    // ---- Phase E: GEMM2 h_agg_pre = N @ hp' (fp16 2-term), s in 2 chunks ----
    const unsigned aA0 = SMB + (unsigned)ATILE + (m0 + (q & 1) * 8 + r8) * 144 + (q >> 1) * 16;
    const unsigned aA1 = aA0 + 16 * 144;
    // B (trans): rows = s, cols = f
    const unsigned bT = ((q & 1) * 8 + r8) * 272u + (unsigned)(n0 + ((q >> 1) & 1) * 8) * 2u;
    const unsigned bH2 = SMB + (unsigned)BHI + bT;
    const unsigned bL2 = SMB + (unsigned)BLO + bT;

    float acc2[2][8][4];
#pragma unroll
    for (int mt = 0; mt < 2; mt++)
#pragma unroll
        for (int nt = 0; nt < 8; nt++)
#pragma unroll
            for (int i = 0; i < 4; i++) acc2[mt][nt][i] = 0.f;

#pragma unroll 1
    for (int h = 0; h < 2; h++) {
        if (h) __syncthreads();
        // stage A tile: counts (+ self-loop) -> fp16 exact, [128 d][64 s], 144B rows
        {
            const int* cw = (const int*)(Sb + CNT8);
            for (int w = t; w < 128 * 16; w += 256) {
                int d = w >> 4, wi = w & 15;
                int word = cw[d * 32 + h * 16 + wi];
                int s0 = h * 64 + wi * 4;
                float f0 = (float)(word & 255)         + ((d == s0)     ? 1.f : 0.f);
                float f1 = (float)((word >> 8) & 255)  + ((d == s0 + 1) ? 1.f : 0.f);
                float f2 = (float)((word >> 16) & 255) + ((d == s0 + 2) ? 1.f : 0.f);
                float f3 = (float)((word >> 24) & 255) + ((d == s0 + 3) ? 1.f : 0.f);
                *(uint2*)(Sb + ATILE + d * 144 + wi * 8) =
                    make_uint2(pack_h2(f0, f1), pack_h2(f2, f3));
            }
        }
        __syncthreads();
#pragma unroll
        for (int kk = 0; kk < 4; kk++) {
            const unsigned ko = (unsigned)kk * 32u;               // A byte offset
            const unsigned bko = (unsigned)((h * 64 + kk * 16) * 272);  // B row offset
            unsigned a0[4], a1[4];
            LDSM4(a0, aA0 + ko);
            LDSM4(a1, aA1 + ko);
#pragma unroll
            for (int p = 0; p < 4; p++) {
                unsigned bh[4], bl[4];
                LDSM4T(bh, bH2 + bko + p * 32);
                LDSM4T(bl, bL2 + bko + p * 32);
                MMA16816(acc2[0][2 * p],     a0, bh[0], bh[1]);
                MMA16816(acc2[0][2 * p + 1], a0, bh[2], bh[3]);
                MMA16816(acc2[1][2 * p],     a1, bh[0], bh[1]);
                MMA16816(acc2[1][2 * p + 1], a1, bh[2], bh[3]);
                MMA16816(acc2[0][2 * p],     a0, bl[0], bl[1]);
                MMA16816(acc2[0][2 * p + 1], a0, bl[2], bl[3]);
                MMA16816(acc2[1][2 * p],     a1, bl[0], bl[1]);
                MMA16816(acc2[1][2 * p + 1], a1, bl[2], bl[3]);
            }
        }
    }
    __syncthreads();   // GEMM2 reads done -> B tiles dead, AGG may be written

    // ---- Phase F: epilogue AGG = relu(rinv[d]*D + b1) ----
    {
        const int rb = lane >> 2, cb = 2 * (lane & 3);
#pragma unroll
        for (int mt = 0; mt < 2; mt++) {
            int row0 = m0 + 16 * mt + rb;
            float rv0 = rinv[row0], rv1 = rinv[row0 + 8];
#pragma unroll
            for (int nt = 0; nt < 8; nt++) {
                int col = n0 + 8 * nt + cb;
                float bb0 = b1s[col], bb1 = b1s[col + 1];
                float v0 = fmaxf(fmaf(rv0, acc2[mt][nt][0], bb0), 0.f);
                float v1 = fmaxf(fmaf(rv0, acc2[mt][nt][1], bb1), 0.f);
                float v2 = fmaxf(fmaf(rv1, acc2[mt][nt][2], bb0), 0.f);
                float v3 = fmaxf(fmaf(rv1, acc2[mt][nt][3], bb1), 0.f);
                *(float2*)(AGG + row0 * HP_ST + col)       = make_float2(v0, v1);
                *(float2*)(AGG + (row0 + 8) * HP_ST + col) = make_float2(v2, v3);
            }
        }
    }
    __syncthreads();

    // ---- Phase G: tval[i] = h[i].Ws, 2 threads per row ----
    {
        int i = t & 127, hf = t >> 7;
        const float4* row = (const float4*)(AGG + i * HP_ST + hf * 64);
        const float4* wsp = (const float4*)(wss + hf * 64);
        float p = 0.f;
#pragma unroll
        for (int c = 0; c < 16; c++) {
            float4 a = row[c], w = wsp[c];
            p += a.x * w.x + a.y * w.y + a.z * w.z + a.w * w.w;
        }
        part[t] = p;
    }
    __syncthreads();
    if (t < 128) {
        float tv = part[t] + part[t + 128];
        tval[t] = tv;
        uvec[t] = rinv[t] * tv;
    }
    __syncthreads();

    // ---- Phase H: score[d] via dense u8 row sweep ----
    if (t < 128) {
        float rd = rinv[t];
        const int* cw = (const int*)(Sb + CNT8);
        float a = 0.f;
#pragma unroll 4
        for (int w0 = 0; w0 < 32; w0++) {
            int w = (w0 + lane) & 31;
            int word = cw[t * 32 + w];
            if (word) {
                int s0 = w * 4;
                a = fmaf((float)(word & 255),         uvec[s0],     a);
                a = fmaf((float)((word >> 8) & 255),  uvec[s0 + 1], a);
                a = fmaf((float)((word >> 16) & 255), uvec[s0 + 2], a);
                a = fmaf((float)((word >> 24) & 255), uvec[s0 + 3], a);
            }
        }
        score[t] = rd * rd * tval[t] + rd * a + bs[0];
    }
    __syncthreads();

    // ---- Phase I: top-K via rank (lax.top_k tie-break) ----
    if (t < 128) {
        float sd = score[t];
        int rank = 0;
        for (int j = 0; j < 128; j++) {
            float sj = score[j];
            rank += (sj > sd) || (sj == sd && j < t);
        }
        wsel[t] = (rank < KSEL) ? (tanhf(sd) * (1.0f / KSEL)) : 0.0f;
    }
    __syncthreads();

    // ---- Phase J: pooled[f] = sum_d wsel[d]*AGG[d][f], 2 threads per f ----
    {
        int f = t & 127, hf = t >> 7;
        const float* base = AGG + hf * 64 * HP_ST + f;
        const float* wsb  = wsel + hf * 64;
        float p = 0.f;
#pragma unroll 8
        for (int d = 0; d < 64; d++) p = fmaf(wsb[d], base[d * HP_ST], p);
        part[t] = p;
    }
    __syncthreads();
    if (t < 128) pooled[t] = part[t] + part[t + 128];
    __syncthreads();

    // ---- Phase K: out = pooled @ Wlin + blin, 2 threads per f ----
    {
        int f = t & 127, hf = t >> 7;
        const float* pl = pooled + hf * 64;
        const float* wl = Wlin + hf * 64 * 128 + f;
        float o = 0.f;
#pragma unroll 8
        for (int k = 0; k < 64; k++) o = fmaf(pl[k], wl[k * 128], o);
        part[t] = o;
    }
    __syncthreads();
    if (t < 128)
        out[(size_t)g * HID + t] = part[t] + part[t + 128] + blin[t];
}

extern "C" void kernel_launch(void* const* d_in, const int* in_sizes, int n_in,
                              void* d_out, int out_size) {
    const float* x    = (const float*)d_in[0];
    const int*   ei   = (const int*)  d_in[1];
    const float* W1   = (const float*)d_in[3];
    const float* b1   = (const float*)d_in[4];
    const float* Ws   = (const float*)d_in[5];
    const float* bs   = (const float*)d_in[6];
    const float* Wlin = (const float*)d_in[7];
    const float* blin = (const float*)d_in[8];
    float* out = (float*)d_out;

    const int E = in_sizes[1] / 2;
    const int* esrc = ei;
    const int* edst = ei + E;

    prep_W_kernel<<<64, 256>>>(W1);

    cudaFuncSetAttribute(sagpool_fused_kernel,
                         cudaFuncAttributeMaxDynamicSharedMemorySize, SMEM_BYTES);
    sagpool_fused_kernel<<<NB, 256, SMEM_BYTES>>>(
        x, esrc, edst, b1, Ws, bs, Wlin, blin, out);
}

// round 10
// speedup vs baseline: 2.2531x; 1.0429x over previous
#include <cuda_runtime.h>
#include <cuda_fp16.h>
#include <cstdint>
#include <stdint.h>
#include <math.h>

#define NB    512
#define NPG   128
#define EPG   2048
#define HID   128
#define KSEL  64

// ---- smem byte map (113,664 B total, 2 CTAs/SM) ----
// Upfront/GEMM1: x0 hi@0 lo@18432 | W hi@36864 lo@55296 | x1 hi@73728 lo@92160
// post-ch0:      CNT8@16384 (16KB, inside dead x0)
// post-GEMM1:    BHI@36864 BLO@71680 (272B rows) ; ATILE@0 (sw128, 16KB)
// post-GEMM2:    AGG fp32 [128][132] @36864 (67,584B)
// misc-early @110592: rinv, b1s, wss      misc-late @0 (floats): tval,uvec,score,wsel,pooled,part
constexpr int XHI1  = 73728;
constexpr int WHIo  = 36864;
constexpr int WLOo  = 55296;
constexpr int CNT8  = 16384;
constexpr int BHIo  = 36864;
constexpr int BLOo  = 71680;
constexpr int AGGo  = 36864;
constexpr int MISCE = 110592;
constexpr int HP_ST = 132;
constexpr int SMEM_BYTES = 113664;

// W1^T hi|lo fp16, 256B rows (full K), written once per launch
__device__ __align__(16) unsigned char g_WT[65536];

__device__ __forceinline__ unsigned smem_u32(const void* p) {
    unsigned a;
    asm("{ .reg .u64 t; cvta.to.shared.u64 t, %1; cvt.u32.u64 %0, t; }" : "=r"(a) : "l"(p));
    return a;
}

#define LDSM4(r, addr) \
    asm volatile("ldmatrix.sync.aligned.m8n8.x4.shared.b16 {%0,%1,%2,%3}, [%4];" \
        : "=r"((r)[0]), "=r"((r)[1]), "=r"((r)[2]), "=r"((r)[3]) : "r"(addr))

#define LDSM4T(r, addr) \
    asm volatile("ldmatrix.sync.aligned.m8n8.x4.trans.shared.b16 {%0,%1,%2,%3}, [%4];" \
        : "=r"((r)[0]), "=r"((r)[1]), "=r"((r)[2]), "=r"((r)[3]) : "r"(addr))

#define MMA16816(c, a, b0, b1) \
    asm volatile("mma.sync.aligned.m16n8k16.row.col.f32.f16.f16.f32 " \
        "{%0,%1,%2,%3},{%4,%5,%6,%7},{%8,%9},{%0,%1,%2,%3};" \
        : "+f"((c)[0]), "+f"((c)[1]), "+f"((c)[2]), "+f"((c)[3]) \
        : "r"((a)[0]), "r"((a)[1]), "r"((a)[2]), "r"((a)[3]), "r"(b0), "r"(b1))

__device__ __forceinline__ unsigned pack_h2(float lo, float hi_) {
    unsigned r;
    asm("cvt.rn.f16x2.f32 %0, %1, %2;" : "=r"(r) : "f"(hi_), "f"(lo));
    return r;
}
__device__ __forceinline__ unsigned pack_hh(__half a, __half b) {
    return ((unsigned)__half_as_ushort(b) << 16) | (unsigned)__half_as_ushort(a);
}

#define SCORE4(wd, sb) do { int _w = (wd); if (_w) { \
    a = fmaf((float)(_w & 255),         uvec[(sb)],     a); \
    a = fmaf((float)((_w >> 8) & 255),  uvec[(sb) + 1], a); \
    a = fmaf((float)((_w >> 16) & 255), uvec[(sb) + 2], a); \
    a = fmaf((float)((_w >> 24) & 255), uvec[(sb) + 3], a); } } while (0)

// ---------------- prep: W1^T -> fp16 hi/lo, 256B rows ----------------
__global__ void prep_W_kernel(const float* __restrict__ W1) {
    int i = blockIdx.x * 256 + threadIdx.x;
    int k = i >> 7, n = i & 127;              // W1[k][n] -> WT[n][k]
    float v = W1[k * 128 + n];
    __half hi = __float2half_rn(v);
    __half lo = __float2half_rn(v - __half2float(hi));
    unsigned off = (unsigned)n * 256u + (unsigned)k * 2u;
    *(__half*)(g_WT + off)          = hi;
    *(__half*)(g_WT + 32768u + off) = lo;
}

// ---------------- main fused kernel ----------------
extern __shared__ float S[];

__global__ void __launch_bounds__(256, 2) sagpool_fused_kernel(
    const float* __restrict__ x,
    const int*   __restrict__ esrc,
    const int*   __restrict__ edst,
    const float* __restrict__ b1,
    const float* __restrict__ Ws,
    const float* __restrict__ bs,
    const float* __restrict__ Wlin,
    const float* __restrict__ blin,
    float*       __restrict__ out)
{
    const int g = blockIdx.x;
    const int t = threadIdx.x;
    const int lane = t & 31;
    const int warp = t >> 5;

    char*  Sb     = (char*)S;
    float* AGG    = (float*)(Sb + AGGo);
    float* rinv   = (float*)(Sb + MISCE);
    float* b1s    = rinv + 128;
    float* wss    = b1s  + 128;
    float* tval   = S;             // misc-late @0 (over dead ATILE)
    float* uvec   = tval  + 128;
    float* score  = uvec  + 128;
    float* wsel   = score + 128;
    float* pooled = wsel  + 128;
    float* part   = pooled + 128;

    // ---- Phase A: upfront global loads — edges (regs), x both chunks, W chunk 0 ----
    const int ebase = g * EPG;
    int sl[8], dl[8];
#pragma unroll
    for (int e = 0; e < 8; e++) {
        int ei = ebase + t + e * 256;
        sl[e] = esrc[ei] & (NPG - 1);
        dl[e] = edst[ei] & (NPG - 1);
    }
    const float* xg = x + (size_t)g * NPG * HID;
#pragma unroll 1
    for (int h = 0; h < 2; h++) {
        const unsigned xb = (unsigned)(h * XHI1);
#pragma unroll
        for (int i = 0; i < 8; i++) {
            int idx = t + i * 256;                 // 0..2047
            int row = idx >> 4, f4 = idx & 15;     // 16 float4 per 64-col chunk row
            float4 v = *(const float4*)(xg + row * HID + h * 64 + f4 * 4);
            __half h0 = __float2half_rn(v.x), h1 = __float2half_rn(v.y);
            __half h2 = __float2half_rn(v.z), h3 = __float2half_rn(v.w);
            *(uint2*)(Sb + xb + row * 144 + f4 * 8) =
                make_uint2(pack_hh(h0, h1), pack_hh(h2, h3));
            *(uint2*)(Sb + xb + 18432 + row * 144 + f4 * 8) =
                make_uint2(pack_h2(v.x - __half2float(h0), v.y - __half2float(h1)),
                           pack_h2(v.z - __half2float(h2), v.w - __half2float(h3)));
        }
    }
    {   // W chunk 0
        int4* wh = (int4*)(Sb + WHIo);
        int4* wl = (int4*)(Sb + WLOo);
        for (int i = t; i < 1024; i += 256) {
            int row = i >> 3, c = i & 7;
            wh[row * 9 + c] = *(const int4*)(g_WT + row * 256 + c * 16);
            wl[row * 9 + c] = *(const int4*)(g_WT + 32768 + row * 256 + c * 16);
        }
    }
    if (t < 128) { b1s[t] = b1[t]; wss[t] = Ws[t]; }
    __syncthreads();

    // ---- Phase B: GEMM1 hp = x@W1 (fp16 3-term split); scatter between chunks ----
    const int m0 = (warp & 3) * 32;
    const int n0 = (warp >> 2) * 64;
    const unsigned q = (unsigned)lane >> 3, r8 = (unsigned)lane & 7;
    const unsigned SMB = smem_u32(S);

    const unsigned rowA  = (m0 + (q & 1) * 8 + r8) * 144 + (q >> 1) * 16;
    const unsigned rowBW = (n0 + ((q >> 1) & 1) * 8 + r8) * 144 + (q & 1) * 16;
    const unsigned bHiB = SMB + WHIo + rowBW;
    const unsigned bLoB = SMB + WLOo + rowBW;

    float acc[2][8][4];
#pragma unroll
    for (int mt = 0; mt < 2; mt++)
#pragma unroll
        for (int nt = 0; nt < 8; nt++)
#pragma unroll
            for (int i = 0; i < 4; i++) acc[mt][nt][i] = 0.f;

#pragma unroll 1
    for (int h = 0; h < 2; h++) {
        if (h == 1) {
            __syncthreads();                       // ch0 MMA reads done
            // zero CNT8 (inside dead x0)
            int4 z = make_int4(0, 0, 0, 0);
            int4* cz = (int4*)(Sb + CNT8);
            for (int i = t; i < 1024; i += 256) cz[i] = z;
            __syncthreads();
            // edge scatter + W chunk-1 restage
            int* cw = (int*)(Sb + CNT8);
#pragma unroll
            for (int e = 0; e < 8; e++)
                atomicAdd(&cw[dl[e] * 32 + (sl[e] >> 2)], 1 << ((sl[e] & 3) * 8));
            int4* wh = (int4*)(Sb + WHIo);
            int4* wl = (int4*)(Sb + WLOo);
            for (int i = t; i < 1024; i += 256) {
                int row = i >> 3, c = i & 7;
                wh[row * 9 + c] = *(const int4*)(g_WT + row * 256 + 128 + c * 16);
                wl[row * 9 + c] = *(const int4*)(g_WT + 32768 + row * 256 + 128 + c * 16);
            }
            __syncthreads();
        }
        const unsigned aHi0 = SMB + (unsigned)(h * XHI1) + rowA;
        const unsigned aHi1 = aHi0 + 16 * 144;
        const unsigned aLo0 = aHi0 + 18432u;
        const unsigned aLo1 = aHi1 + 18432u;
#pragma unroll
        for (int kk = 0; kk < 4; kk++) {
            const unsigned ko = (unsigned)kk * 32u;
            unsigned ah0[4], ah1[4], al0[4], al1[4];
            LDSM4(ah0, aHi0 + ko);
            LDSM4(ah1, aHi1 + ko);
            LDSM4(al0, aLo0 + ko);
            LDSM4(al1, aLo1 + ko);
#pragma unroll
            for (int p = 0; p < 4; p++) {
                unsigned bh[4], bl[4];
                LDSM4(bh, bHiB + p * (16 * 144) + ko);
                LDSM4(bl, bLoB + p * (16 * 144) + ko);
                MMA16816(acc[0][2 * p],     ah0, bh[0], bh[1]);
                MMA16816(acc[0][2 * p + 1], ah0, bh[2], bh[3]);
                MMA16816(acc[1][2 * p],     ah1, bh[0], bh[1]);
                MMA16816(acc[1][2 * p + 1], ah1, bh[2], bh[3]);
                MMA16816(acc[0][2 * p],     al0, bh[0], bh[1]);
                MMA16816(acc[0][2 * p + 1], al0, bh[2], bh[3]);
                MMA16816(acc[1][2 * p],     al1, bh[0], bh[1]);
                MMA16816(acc[1][2 * p + 1], al1, bh[2], bh[3]);
                MMA16816(acc[0][2 * p],     ah0, bl[0], bl[1]);
                MMA16816(acc[0][2 * p + 1], ah0, bl[2], bl[3]);
                MMA16816(acc[1][2 * p],     ah1, bl[0], bl[1]);
                MMA16816(acc[1][2 * p + 1], ah1, bl[2], bl[3]);
            }
        }
    }
    // degrees from CNT8 row sums (+1 self loop)
    if (t < 128) {
        const int* cw = (const int*)(Sb + CNT8);
        int deg = 1;
#pragma unroll
        for (int w = 0; w < 32; w++) deg = __dp4a(cw[t * 32 + w], 0x01010101, deg);
        rinv[t] = rsqrtf((float)deg);
    }
    __syncthreads();   // GEMM1 reads done + rinv visible

    // ---- Phase C: hp' = rinv[s]*hp -> node-major [s][f] fp16 hi/lo, 272B rows ----
    {
        const int rb = lane >> 2, cb = 2 * (lane & 3);
#pragma unroll
        for (int mt = 0; mt < 2; mt++) {
            int row0 = m0 + 16 * mt + rb;
            float rv0 = rinv[row0], rv1 = rinv[row0 + 8];
#pragma unroll
            for (int nt = 0; nt < 8; nt++) {
                int col = n0 + 8 * nt + cb;
                float v0 = acc[mt][nt][0] * rv0, v1 = acc[mt][nt][1] * rv0;
                float v2 = acc[mt][nt][2] * rv1, v3 = acc[mt][nt][3] * rv1;
                __half h0 = __float2half_rn(v0), h1 = __float2half_rn(v1);
                __half h2 = __float2half_rn(v2), h3 = __float2half_rn(v3);
                unsigned o0 = row0 * 272u + col * 2u;
                unsigned o1 = (row0 + 8) * 272u + col * 2u;
                *(unsigned*)(Sb + BHIo + o0) = pack_hh(h0, h1);
                *(unsigned*)(Sb + BHIo + o1) = pack_hh(h2, h3);
                *(unsigned*)(Sb + BLOo + o0) =
                    pack_h2(v0 - __half2float(h0), v1 - __half2float(h1));
                *(unsigned*)(Sb + BLOo + o1) =
                    pack_h2(v2 - __half2float(h2), v3 - __half2float(h3));
            }
        }
    }
    __syncthreads();

    // ---- Phase E: GEMM2 = N @ hp' (fp16 2-term), ATILE sw128 @0, s in 2 chunks ----
    const unsigned rA0 = (unsigned)(m0 + (q & 1) * 8 + r8);
    const unsigned rA1 = rA0 + 16;
    const unsigned sw0 = rA0 & 7, sw1 = rA1 & 7;
    const unsigned qh = q >> 1;
    const unsigned bT = ((q & 1) * 8 + r8) * 272u + (unsigned)(n0 + ((q >> 1) & 1) * 8) * 2u;
    const unsigned bH2 = SMB + BHIo + bT;
    const unsigned bL2 = SMB + BLOo + bT;

    float acc2[2][8][4];
#pragma unroll
    for (int mt = 0; mt < 2; mt++)
#pragma unroll
        for (int nt = 0; nt < 8; nt++)
#pragma unroll
            for (int i = 0; i < 4; i++) acc2[mt][nt][i] = 0.f;

#pragma unroll 1
    for (int h = 0; h < 2; h++) {
        if (h) __syncthreads();
        // stage ATILE: counts (+ self-loop) -> fp16 exact, [128 d][64 s], sw128 rows
        {
            const int* cw = (const int*)(Sb + CNT8);
            for (int w = t; w < 2048; w += 256) {
                int d = w >> 4, wi = w & 15;
                int word = cw[d * 32 + h * 16 + wi];
                int s0 = h * 64 + wi * 4;
                float f0 = (float)(word & 255)         + ((d == s0)     ? 1.f : 0.f);
                float f1 = (float)((word >> 8) & 255)  + ((d == s0 + 1) ? 1.f : 0.f);
                float f2 = (float)((word >> 16) & 255) + ((d == s0 + 2) ? 1.f : 0.f);
                float f3 = (float)((word >> 24) & 255) + ((d == s0 + 3) ? 1.f : 0.f);
                unsigned swz = (unsigned)((((wi >> 1) ^ (d & 7)) << 4) + (wi & 1) * 8);
                *(uint2*)(Sb + d * 128 + swz) =
                    make_uint2(pack_h2(f0, f1), pack_h2(f2, f3));
            }
        }
        __syncthreads();
#pragma unroll
        for (int kk = 0; kk < 4; kk++) {
            const unsigned gA = (unsigned)(kk * 2) + qh;
            const unsigned addrA0 = SMB + rA0 * 128 + ((gA ^ sw0) << 4);
            const unsigned addrA1 = SMB + rA1 * 128 + ((gA ^ sw1) << 4);
            const unsigned bko = (unsigned)((h * 64 + kk * 16) * 272);
            unsigned a0[4], a1[4];
            LDSM4(a0, addrA0);
            LDSM4(a1, addrA1);
#pragma unroll
            for (int p = 0; p < 4; p++) {
                unsigned bh[4], bl[4];
                LDSM4T(bh, bH2 + bko + p * 32);
                LDSM4T(bl, bL2 + bko + p * 32);
                MMA16816(acc2[0][2 * p],     a0, bh[0], bh[1]);
                MMA16816(acc2[0][2 * p + 1], a0, bh[2], bh[3]);
                MMA16816(acc2[1][2 * p],     a1, bh[0], bh[1]);
                MMA16816(acc2[1][2 * p + 1], a1, bh[2], bh[3]);
                MMA16816(acc2[0][2 * p],     a0, bl[0], bl[1]);
                MMA16816(acc2[0][2 * p + 1], a0, bl[2], bl[3]);
                MMA16816(acc2[1][2 * p],     a1, bl[0], bl[1]);
                MMA16816(acc2[1][2 * p + 1], a1, bl[2], bl[3]);
            }
        }
    }
    __syncthreads();   // GEMM2 reads done -> B tiles dead, AGG may be written

    // ---- Phase F: epilogue AGG = relu(rinv[d]*D + b1) ----
    {
        const int rb = lane >> 2, cb = 2 * (lane & 3);
#pragma unroll
        for (int mt = 0; mt < 2; mt++) {
            int row0 = m0 + 16 * mt + rb;
            float rv0 = rinv[row0], rv1 = rinv[row0 + 8];
#pragma unroll
            for (int nt = 0; nt < 8; nt++) {
                int col = n0 + 8 * nt + cb;
                float bb0 = b1s[col], bb1 = b1s[col + 1];
                float v0 = fmaxf(fmaf(rv0, acc2[mt][nt][0], bb0), 0.f);
                float v1 = fmaxf(fmaf(rv0, acc2[mt][nt][1], bb1), 0.f);
                float v2 = fmaxf(fmaf(rv1, acc2[mt][nt][2], bb0), 0.f);
                float v3 = fmaxf(fmaf(rv1, acc2[mt][nt][3], bb1), 0.f);
                *(float2*)(AGG + row0 * HP_ST + col)       = make_float2(v0, v1);
                *(float2*)(AGG + (row0 + 8) * HP_ST + col) = make_float2(v2, v3);
            }
        }
    }
    __syncthreads();

    // ---- Phase G: tval[i] = h[i].Ws, 2 threads per row ----
    {
        int i = t & 127, hf = t >> 7;
        const float4* row = (const float4*)(AGG + i * HP_ST + hf * 64);
        const float4* wsp = (const float4*)(wss + hf * 64);
        float p = 0.f;
#pragma unroll
        for (int c = 0; c < 16; c++) {
            float4 a = row[c], w = wsp[c];
            p += a.x * w.x + a.y * w.y + a.z * w.z + a.w * w.w;
        }
        part[t] = p;
    }
    __syncthreads();
    if (t < 128) {
        float tv = part[t] + part[t + 128];
        tval[t] = tv;
        uvec[t] = rinv[t] * tv;
    }
    __syncthreads();

    // ---- Phase H: score[d] via dense u8 row sweep (int4, bank-rotated) ----
    if (t < 128) {
        float rd = rinv[t];
        const int4* cw4 = (const int4*)(Sb + CNT8 + t * 128);
        float a = 0.f;
#pragma unroll
        for (int w4 = 0; w4 < 8; w4++) {
            int slot = (w4 + (t & 7)) & 7;
            int4 ww = cw4[slot];
            int sb = slot * 16;
            SCORE4(ww.x, sb);
            SCORE4(ww.y, sb + 4);
            SCORE4(ww.z, sb + 8);
            SCORE4(ww.w, sb + 12);
        }
        score[t] = rd * rd * tval[t] + rd * a + bs[0];
    }
    __syncthreads();

    // ---- Phase I: top-K via rank (lax.top_k tie-break), float4 sweep ----
    if (t < 128) {
        float sd = score[t];
        int rank = 0;
        const float4* sc4 = (const float4*)score;
#pragma unroll
        for (int j4 = 0; j4 < 32; j4++) {
            float4 s4 = sc4[j4];
            int j = j4 * 4;
            rank += (s4.x > sd) || (s4.x == sd && j     < t);
            rank += (s4.y > sd) || (s4.y == sd && j + 1 < t);
            rank += (s4.z > sd) || (s4.z == sd && j + 2 < t);
            rank += (s4.w > sd) || (s4.w == sd && j + 3 < t);
        }
        wsel[t] = (rank < KSEL) ? (tanhf(sd) * (1.0f / KSEL)) : 0.0f;
    }
    __syncthreads();

    // ---- Phase J: pooled[f] = sum_d wsel[d]*AGG[d][f], 2 threads per f ----
    {
        int f = t & 127, hf = t >> 7;
        const float* base = AGG + hf * 64 * HP_ST + f;
        const float* wsb  = wsel + hf * 64;
        float p = 0.f;
#pragma unroll 8
        for (int d = 0; d < 64; d++) p = fmaf(wsb[d], base[d * HP_ST], p);
        part[t] = p;
    }
    __syncthreads();
    if (t < 128) pooled[t] = part[t] + part[t + 128];
    __syncthreads();

    // ---- Phase K: out = pooled @ Wlin + blin, 2 threads per f ----
    {
        int f = t & 127, hf = t >> 7;
        const float* pl = pooled + hf * 64;
        const float* wl = Wlin + hf * 64 * 128 + f;
        float o = 0.f;
#pragma unroll 16
        for (int k = 0; k < 64; k++) o = fmaf(pl[k], wl[k * 128], o);
        part[t] = o;
    }
    __syncthreads();
    if (t < 128)
        out[(size_t)g * HID + t] = part[t] + part[t + 128] + blin[t];
}

extern "C" void kernel_launch(void* const* d_in, const int* in_sizes, int n_in,
                              void* d_out, int out_size) {
    const float* x    = (const float*)d_in[0];
    const int*   ei   = (const int*)  d_in[1];
    const float* W1   = (const float*)d_in[3];
    const float* b1   = (const float*)d_in[4];
    const float* Ws   = (const float*)d_in[5];
    const float* bs   = (const float*)d_in[6];
    const float* Wlin = (const float*)d_in[7];
    const float* blin = (const float*)d_in[8];
    float* out = (float*)d_out;

    const int E = in_sizes[1] / 2;
    const int* esrc = ei;
    const int* edst = ei + E;

    prep_W_kernel<<<64, 256>>>(W1);

    cudaFuncSetAttribute(sagpool_fused_kernel,
                         cudaFuncAttributeMaxDynamicSharedMemorySize, SMEM_BYTES);
    sagpool_fused_kernel<<<NB, 256, SMEM_BYTES>>>(
        x, esrc, edst, b1, Ws, bs, Wlin, blin, out);
}

// round 11
// speedup vs baseline: 2.4131x; 1.0710x over previous
#include <cuda_runtime.h>
#include <cuda_fp16.h>
#include <cstdint>
#include <stdint.h>
#include <math.h>

#define NB    512
#define NPG   128
#define EPG   2048
#define HID   128
#define KSEL  64

// ---- smem byte map (113,664 B, 2 CTAs/SM) ----
// Phase A / GEMM1: x0 hi@0 lo@18432 | W hi@36864 lo@55296 | x1 hi@73728 lo@92160
// mid-GEMM1 (x0 dead): ATILE fp16 [128][256B swizzled] @0 (32KB) -- scatter target
// post-GEMM1: B tiles BHI@36864 BLO@71680 (272B rows); misc-late @32768
// post-GEMM2: AGG fp32 [128][132] @36864
constexpr int MISCL = 32768;
constexpr int WHIo  = 36864;
constexpr int WLOo  = 55296;
constexpr int BHIo  = 36864;
constexpr int BLOo  = 71680;
constexpr int AGGo  = 36864;
constexpr int XHI1  = 73728;
constexpr int MISCE = 110592;
constexpr int HP_ST = 132;
constexpr int SMEM_BYTES = 113664;

// W1^T hi|lo fp16, 256B rows (full K), written once per launch
__device__ __align__(16) unsigned char g_WT[65536];

__device__ __forceinline__ unsigned smem_u32(const void* p) {
    unsigned a;
    asm("{ .reg .u64 t; cvta.to.shared.u64 t, %1; cvt.u32.u64 %0, t; }" : "=r"(a) : "l"(p));
    return a;
}

#define LDSM4(r, addr) \
    asm volatile("ldmatrix.sync.aligned.m8n8.x4.shared.b16 {%0,%1,%2,%3}, [%4];" \
        : "=r"((r)[0]), "=r"((r)[1]), "=r"((r)[2]), "=r"((r)[3]) : "r"(addr))

#define LDSM4T(r, addr) \
    asm volatile("ldmatrix.sync.aligned.m8n8.x4.trans.shared.b16 {%0,%1,%2,%3}, [%4];" \
        : "=r"((r)[0]), "=r"((r)[1]), "=r"((r)[2]), "=r"((r)[3]) : "r"(addr))

#define MMA16816(c, a, b0, b1) \
    asm volatile("mma.sync.aligned.m16n8k16.row.col.f32.f16.f16.f32 " \
        "{%0,%1,%2,%3},{%4,%5,%6,%7},{%8,%9},{%0,%1,%2,%3};" \
        : "+f"((c)[0]), "+f"((c)[1]), "+f"((c)[2]), "+f"((c)[3]) \
        : "r"((a)[0]), "r"((a)[1]), "r"((a)[2]), "r"((a)[3]), "r"(b0), "r"(b1))

__device__ __forceinline__ unsigned pack_h2(float lo, float hi_) {
    unsigned r;
    asm("cvt.rn.f16x2.f32 %0, %1, %2;" : "=r"(r) : "f"(hi_), "f"(lo));
    return r;
}
__device__ __forceinline__ unsigned pack_hh(__half a, __half b) {
    return ((unsigned)__half_as_ushort(b) << 16) | (unsigned)__half_as_ushort(a);
}
// ATILE swizzled 16B-group index for (row d, group g)
__device__ __forceinline__ unsigned asw(unsigned g, unsigned d) {
    return (g & 8u) | ((g & 7u) ^ (d & 7u));
}

// ---------------- prep: W1^T -> fp16 hi/lo, 256B rows ----------------
__global__ void prep_W_kernel(const float* __restrict__ W1) {
    int i = blockIdx.x * 256 + threadIdx.x;
    int k = i >> 7, n = i & 127;              // W1[k][n] -> WT[n][k]
    float v = W1[k * 128 + n];
    __half hi = __float2half_rn(v);
    __half lo = __float2half_rn(v - __half2float(hi));
    unsigned off = (unsigned)n * 256u + (unsigned)k * 2u;
    *(__half*)(g_WT + off)          = hi;
    *(__half*)(g_WT + 32768u + off) = lo;
}

// ---------------- main fused kernel ----------------
extern __shared__ float S[];

__global__ void __launch_bounds__(256, 2) sagpool_fused_kernel(
    const float* __restrict__ x,
    const int*   __restrict__ esrc,
    const int*   __restrict__ edst,
    const float* __restrict__ b1,
    const float* __restrict__ Ws,
    const float* __restrict__ bs,
    const float* __restrict__ Wlin,
    const float* __restrict__ blin,
    float*       __restrict__ out)
{
    const int g = blockIdx.x;
    const int t = threadIdx.x;
    const int lane = t & 31;
    const int warp = t >> 5;

    char*  Sb     = (char*)S;
    float* AGG    = (float*)(Sb + AGGo);
    float* rinv   = (float*)(Sb + MISCE);
    float* b1s    = rinv + 128;
    float* wss    = b1s  + 128;
    float* tval   = (float*)(Sb + MISCL);
    float* uvec   = tval  + 128;
    float* score  = uvec  + 128;
    float* wsel   = score + 128;
    float* pooled = wsel  + 128;
    float* part   = pooled + 128;

    // ---- Phase A: upfront loads — edges (regs), x both chunks, W chunk 0 ----
    const int ebase = g * EPG;
    int sl[8], dl[8];
#pragma unroll
    for (int e = 0; e < 8; e++) {
        int ei = ebase + t + e * 256;
        sl[e] = esrc[ei] & (NPG - 1);
        dl[e] = edst[ei] & (NPG - 1);
    }
    const float* xg = x + (size_t)g * NPG * HID;
#pragma unroll 1
    for (int h = 0; h < 2; h++) {
        const unsigned xb = (unsigned)(h * XHI1);
#pragma unroll
        for (int i = 0; i < 8; i++) {
            int idx = t + i * 256;
            int row = idx >> 4, f4 = idx & 15;
            float4 v = *(const float4*)(xg + row * HID + h * 64 + f4 * 4);
            __half h0 = __float2half_rn(v.x), h1 = __float2half_rn(v.y);
            __half h2 = __float2half_rn(v.z), h3 = __float2half_rn(v.w);
            *(uint2*)(Sb + xb + row * 144 + f4 * 8) =
                make_uint2(pack_hh(h0, h1), pack_hh(h2, h3));
            *(uint2*)(Sb + xb + 18432 + row * 144 + f4 * 8) =
                make_uint2(pack_h2(v.x - __half2float(h0), v.y - __half2float(h1)),
                           pack_h2(v.z - __half2float(h2), v.w - __half2float(h3)));
        }
    }
    {   // W chunk 0
        int4* wh = (int4*)(Sb + WHIo);
        int4* wl = (int4*)(Sb + WLOo);
        for (int i = t; i < 1024; i += 256) {
            int row = i >> 3, c = i & 7;
            wh[row * 9 + c] = *(const int4*)(g_WT + row * 256 + c * 16);
            wl[row * 9 + c] = *(const int4*)(g_WT + 32768 + row * 256 + c * 16);
        }
    }
    if (t < 128) { b1s[t] = b1[t]; wss[t] = Ws[t]; }
    __syncthreads();

    // ---- Phase B: GEMM1 hp = x@W1 (fp16 3-term split); ATILE built between chunks ----
    const int m0 = (warp & 3) * 32;
    const int n0 = (warp >> 2) * 64;
    const unsigned q = (unsigned)lane >> 3, r8 = (unsigned)lane & 7;
    const unsigned qh = q >> 1;
    const unsigned SMB = smem_u32(S);

    const unsigned rowA  = (m0 + (q & 1) * 8 + r8) * 144 + (q >> 1) * 16;
    const unsigned rowBW = (n0 + ((q >> 1) & 1) * 8 + r8) * 144 + (q & 1) * 16;
    const unsigned bHiB = SMB + WHIo + rowBW;
    const unsigned bLoB = SMB + WLOo + rowBW;

    float acc[2][8][4];
#pragma unroll
    for (int mt = 0; mt < 2; mt++)
#pragma unroll
        for (int nt = 0; nt < 8; nt++)
#pragma unroll
            for (int i = 0; i < 4; i++) acc[mt][nt][i] = 0.f;

#pragma unroll 1
    for (int h = 0; h < 2; h++) {
        if (h == 1) {
            __syncthreads();                       // ch0 MMA reads done
            // zero ATILE (32KB over dead x0) + W chunk-1 restage
            {
                int4 z = make_int4(0, 0, 0, 0);
                int4* az = (int4*)Sb;
                for (int i = t; i < 2048; i += 256) az[i] = z;
                int4* wh = (int4*)(Sb + WHIo);
                int4* wl = (int4*)(Sb + WLOo);
                for (int i = t; i < 1024; i += 256) {
                    int row = i >> 3, c = i & 7;
                    wh[row * 9 + c] = *(const int4*)(g_WT + row * 256 + 128 + c * 16);
                    wl[row * 9 + c] = *(const int4*)(g_WT + 32768 + row * 256 + 128 + c * 16);
                }
            }
            __syncthreads();
            // scatter edges directly into fp16 ATILE (+1.0 each, exact)
            {
                const unsigned short one = 0x3C00;
#pragma unroll
                for (int e = 0; e < 8; e++) {
                    unsigned d = (unsigned)dl[e], s = (unsigned)sl[e];
                    unsigned addr = SMB + d * 256u + (asw(s >> 3, d) << 4) + (s & 7u) * 2u;
                    asm volatile("red.shared.add.noftz.f16 [%0], %1;"
                                 :: "r"(addr), "h"(one) : "memory");
                }
            }
            __syncthreads();                       // scatter visible before ch1+rinv
        }
        const unsigned aHi0 = SMB + (unsigned)(h * XHI1) + rowA;
        const unsigned aHi1 = aHi0 + 16 * 144;
        const unsigned aLo0 = aHi0 + 18432u;
        const unsigned aLo1 = aHi1 + 18432u;
#pragma unroll
        for (int kk = 0; kk < 4; kk++) {
            const unsigned ko = (unsigned)kk * 32u;
            unsigned ah0[4], ah1[4], al0[4], al1[4];
            LDSM4(ah0, aHi0 + ko);
            LDSM4(ah1, aHi1 + ko);
            LDSM4(al0, aLo0 + ko);
            LDSM4(al1, aLo1 + ko);
#pragma unroll
            for (int p = 0; p < 4; p++) {
                unsigned bh[4], bl[4];
                LDSM4(bh, bHiB + p * (16 * 144) + ko);
                LDSM4(bl, bLoB + p * (16 * 144) + ko);
                MMA16816(acc[0][2 * p],     ah0, bh[0], bh[1]);
                MMA16816(acc[0][2 * p + 1], ah0, bh[2], bh[3]);
                MMA16816(acc[1][2 * p],     ah1, bh[0], bh[1]);
                MMA16816(acc[1][2 * p + 1], ah1, bh[2], bh[3]);
                MMA16816(acc[0][2 * p],     al0, bh[0], bh[1]);
                MMA16816(acc[0][2 * p + 1], al0, bh[2], bh[3]);
                MMA16816(acc[1][2 * p],     al1, bh[0], bh[1]);
                MMA16816(acc[1][2 * p + 1], al1, bh[2], bh[3]);
                MMA16816(acc[0][2 * p],     ah0, bl[0], bl[1]);
                MMA16816(acc[0][2 * p + 1], ah0, bl[2], bl[3]);
                MMA16816(acc[1][2 * p],     ah1, bl[0], bl[1]);
                MMA16816(acc[1][2 * p + 1], ah1, bl[2], bl[3]);
            }
        }
    }
    // degrees from fp16 row sums (+1 self loop); add self-loop to ATILE (own row only)
    if (t < 128) {
        const uint4* row = (const uint4*)(Sb + t * 256);
        __half2 s2 = __float2half2_rn(0.f);
#pragma unroll
        for (int gg = 0; gg < 16; gg++) {
            uint4 v = row[asw(gg, t)];
            s2 = __hadd2(s2, *(__half2*)&v.x);
            s2 = __hadd2(s2, *(__half2*)&v.y);
            s2 = __hadd2(s2, *(__half2*)&v.z);
            s2 = __hadd2(s2, *(__half2*)&v.w);
        }
        float deg = 1.f + __low2float(s2) + __high2float(s2);
        rinv[t] = rsqrtf(deg);
        __half* sp = (__half*)(Sb + t * 256 + (asw((unsigned)t >> 3, t) << 4) + (t & 7) * 2);
        *sp = __hadd(*sp, __float2half_rn(1.f));   // ATILE = N + I
    }
    __syncthreads();   // GEMM1 reads done + rinv/ATILE visible

    // ---- Phase C: hp' = rinv[s]*hp -> node-major [s][f] fp16 hi/lo, 272B rows ----
    {
        const int rb = lane >> 2, cb = 2 * (lane & 3);
#pragma unroll
        for (int mt = 0; mt < 2; mt++) {
            int row0 = m0 + 16 * mt + rb;
            float rv0 = rinv[row0], rv1 = rinv[row0 + 8];
#pragma unroll
            for (int nt = 0; nt < 8; nt++) {
                int col = n0 + 8 * nt + cb;
                float v0 = acc[mt][nt][0] * rv0, v1 = acc[mt][nt][1] * rv0;
                float v2 = acc[mt][nt][2] * rv1, v3 = acc[mt][nt][3] * rv1;
                __half h0 = __float2half_rn(v0), h1 = __float2half_rn(v1);
                __half h2 = __float2half_rn(v2), h3 = __float2half_rn(v3);
                unsigned o0 = row0 * 272u + col * 2u;
                unsigned o1 = (row0 + 8) * 272u + col * 2u;
                *(unsigned*)(Sb + BHIo + o0) = pack_hh(h0, h1);
                *(unsigned*)(Sb + BHIo + o1) = pack_hh(h2, h3);
                *(unsigned*)(Sb + BLOo + o0) =
                    pack_h2(v0 - __half2float(h0), v1 - __half2float(h1));
                *(unsigned*)(Sb + BLOo + o1) =
                    pack_h2(v2 - __half2float(h2), v3 - __half2float(h3));
            }
        }
    }
    __syncthreads();

    // ---- Phase E: GEMM2 = (N+I-diagfix...) no: = ATILE @ hp' minus nothing —
    //      ATILE = N+I and GEMM2 computes (N+I)@hp' ... but we need N@hp' + self.
    //      (N+I)@hp' = N@hp' + hp'[d]  == exactly the self-loop term rinv_d*hp_d
    //      after the rinv_d epilogue scale: rinv_d*(N+I)@hp' = correct GCN aggregate.
    const unsigned rA0 = (unsigned)(m0 + (q & 1) * 8 + r8);
    const unsigned rA1 = rA0 + 16;
    const unsigned bT = ((q & 1) * 8 + r8) * 272u + (unsigned)(n0 + ((q >> 1) & 1) * 8) * 2u;
    const unsigned bH2 = SMB + BHIo + bT;
    const unsigned bL2 = SMB + BLOo + bT;

    float acc2[2][8][4];
#pragma unroll
    for (int mt = 0; mt < 2; mt++)
#pragma unroll
        for (int nt = 0; nt < 8; nt++)
#pragma unroll
            for (int i = 0; i < 4; i++) acc2[mt][nt][i] = 0.f;

#pragma unroll
    for (int kk = 0; kk < 8; kk++) {
        const unsigned gA = (unsigned)(kk * 2) + qh;
        const unsigned addrA0 = SMB + rA0 * 256 + (asw(gA, rA0) << 4);
        const unsigned addrA1 = SMB + rA1 * 256 + (asw(gA, rA1) << 4);
        const unsigned bko = (unsigned)(kk * 16 * 272);
        unsigned a0[4], a1[4];
        LDSM4(a0, addrA0);
        LDSM4(a1, addrA1);
#pragma unroll
        for (int p = 0; p < 4; p++) {
            unsigned bh[4], bl[4];
            LDSM4T(bh, bH2 + bko + p * 32);
            LDSM4T(bl, bL2 + bko + p * 32);
            MMA16816(acc2[0][2 * p],     a0, bh[0], bh[1]);
            MMA16816(acc2[0][2 * p + 1], a0, bh[2], bh[3]);
            MMA16816(acc2[1][2 * p],     a1, bh[0], bh[1]);
            MMA16816(acc2[1][2 * p + 1], a1, bh[2], bh[3]);
            MMA16816(acc2[0][2 * p],     a0, bl[0], bl[1]);
            MMA16816(acc2[0][2 * p + 1], a0, bl[2], bl[3]);
            MMA16816(acc2[1][2 * p],     a1, bl[0], bl[1]);
            MMA16816(acc2[1][2 * p + 1], a1, bl[2], bl[3]);
        }
    }
    __syncthreads();   // GEMM2 reads done -> B tiles dead, AGG may be written

    // ---- Phase F: epilogue AGG = relu(rinv[d]*D + b1) ----
    {
        const int rb = lane >> 2, cb = 2 * (lane & 3);
#pragma unroll
        for (int mt = 0; mt < 2; mt++) {
            int row0 = m0 + 16 * mt + rb;
            float rv0 = rinv[row0], rv1 = rinv[row0 + 8];
#pragma unroll
            for (int nt = 0; nt < 8; nt++) {
                int col = n0 + 8 * nt + cb;
                float bb0 = b1s[col], bb1 = b1s[col + 1];
                float v0 = fmaxf(fmaf(rv0, acc2[mt][nt][0], bb0), 0.f);
                float v1 = fmaxf(fmaf(rv0, acc2[mt][nt][1], bb1), 0.f);
                float v2 = fmaxf(fmaf(rv1, acc2[mt][nt][2], bb0), 0.f);
                float v3 = fmaxf(fmaf(rv1, acc2[mt][nt][3], bb1), 0.f);
                *(float2*)(AGG + row0 * HP_ST + col)       = make_float2(v0, v1);
                *(float2*)(AGG + (row0 + 8) * HP_ST + col) = make_float2(v2, v3);
            }
        }
    }
    __syncthreads();

    // ---- Phase G: tval[i] = h[i].Ws, 2 threads per row ----
    {
        int i = t & 127, hf = t >> 7;
        const float4* row = (const float4*)(AGG + i * HP_ST + hf * 64);
        const float4* wsp = (const float4*)(wss + hf * 64);
        float p = 0.f;
#pragma unroll
        for (int c = 0; c < 16; c++) {
            float4 a = row[c], w = wsp[c];
            p += a.x * w.x + a.y * w.y + a.z * w.z + a.w * w.w;
        }
        part[t] = p;
    }
    __syncthreads();
    if (t < 128) {
        float tv = part[t] + part[t + 128];
        tval[t] = tv;
        uvec[t] = rinv[t] * tv;
    }
    __syncthreads();

    // ---- Phase H: score[d] = rinv[d]*<ATILE[d], uvec> + bs (diag absorbs self term) ----
    {
        int d = t & 127, hf = t >> 7;
        const char* rowb = Sb + d * 256;
        float a = 0.f;
#pragma unroll
        for (int j = 0; j < 8; j++) {
            int jj = (j + (d >> 3)) & 7;
            int gg = hf * 8 + jj;
            uint4 v = *(const uint4*)(rowb + (asw((unsigned)gg, (unsigned)d) << 4));
            const float* uv = uvec + gg * 8;
            float2 c0 = __half22float2(*(__half2*)&v.x);
            float2 c1 = __half22float2(*(__half2*)&v.y);
            float2 c2 = __half22float2(*(__half2*)&v.z);
            float2 c3 = __half22float2(*(__half2*)&v.w);
            a = fmaf(c0.x, uv[0], a); a = fmaf(c0.y, uv[1], a);
            a = fmaf(c1.x, uv[2], a); a = fmaf(c1.y, uv[3], a);
            a = fmaf(c2.x, uv[4], a); a = fmaf(c2.y, uv[5], a);
            a = fmaf(c3.x, uv[6], a); a = fmaf(c3.y, uv[7], a);
        }
        part[t] = a;
    }
    __syncthreads();
    if (t < 128)
        score[t] = rinv[t] * (part[t] + part[t + 128]) + bs[0];
    __syncthreads();

    // ---- Phase I: top-K via rank (lax.top_k tie-break), float4 sweep ----
    if (t < 128) {
        float sd = score[t];
        int rank = 0;
        const float4* sc4 = (const float4*)score;
#pragma unroll
        for (int j4 = 0; j4 < 32; j4++) {
            float4 s4 = sc4[j4];
            int j = j4 * 4;
            rank += (s4.x > sd) || (s4.x == sd && j     < t);
            rank += (s4.y > sd) || (s4.y == sd && j + 1 < t);
            rank += (s4.z > sd) || (s4.z == sd && j + 2 < t);
            rank += (s4.w > sd) || (s4.w == sd && j + 3 < t);
        }
        wsel[t] = (rank < KSEL) ? (tanhf(sd) * (1.0f / KSEL)) : 0.0f;
    }
    __syncthreads();

    // ---- Phase J: pooled[f] = sum_d wsel[d]*AGG[d][f], 2 threads per f ----
    {
        int f = t & 127, hf = t >> 7;
        const float* base = AGG + hf * 64 * HP_ST + f;
        const float* wsb  = wsel + hf * 64;
        float p = 0.f;
#pragma unroll 8
        for (int d = 0; d < 64; d++) p = fmaf(wsb[d], base[d * HP_ST], p);
        part[t] = p;
    }
    __syncthreads();
    if (t < 128) pooled[t] = part[t] + part[t + 128];
    __syncthreads();

    // ---- Phase K: out = pooled @ Wlin + blin, 2 threads per f ----
    {
        int f = t & 127, hf = t >> 7;
        const float* pl = pooled + hf * 64;
        const float* wl = Wlin + hf * 64 * 128 + f;
        float o = 0.f;
#pragma unroll 16
        for (int k = 0; k < 64; k++) o = fmaf(pl[k], wl[k * 128], o);
        part[t] = o;
    }
    __syncthreads();
    if (t < 128)
        out[(size_t)g * HID + t] = part[t] + part[t + 128] + blin[t];
}

extern "C" void kernel_launch(void* const* d_in, const int* in_sizes, int n_in,
                              void* d_out, int out_size) {
    const float* x    = (const float*)d_in[0];
    const int*   ei   = (const int*)  d_in[1];
    const float* W1   = (const float*)d_in[3];
    const float* b1   = (const float*)d_in[4];
    const float* Ws   = (const float*)d_in[5];
    const float* bs   = (const float*)d_in[6];
    const float* Wlin = (const float*)d_in[7];
    const float* blin = (const float*)d_in[8];
    float* out = (float*)d_out;

    const int E = in_sizes[1] / 2;
    const int* esrc = ei;
    const int* edst = ei + E;

    prep_W_kernel<<<64, 256>>>(W1);

    cudaFuncSetAttribute(sagpool_fused_kernel,
                         cudaFuncAttributeMaxDynamicSharedMemorySize, SMEM_BYTES);
    sagpool_fused_kernel<<<NB, 256, SMEM_BYTES>>>(
        x, esrc, edst, b1, Ws, bs, Wlin, blin, out);
}

// round 12
// speedup vs baseline: 2.4512x; 1.0158x over previous
#include <cuda_runtime.h>
#include <cuda_fp16.h>
#include <cstdint>
#include <stdint.h>
#include <math.h>

#define NB    512
#define NPG   128
#define EPG   2048
#define HID   128
#define KSEL  64

// ---- smem byte map (113,664 B, 2 CTAs/SM) ----
// Phase A / GEMM1: x0 hi@0 lo@18432 | W hi@36864 lo@55296 | x1 hi@73728 lo@92160
// mid-GEMM1 (x0 dead): ATILE fp16 [128][256B swizzled] @0 (32KB) -- scatter target
// post-GEMM1: B tiles BHI@36864 BLO@71680 (272B rows); misc-late @32768
// post-GEMM2: AGG fp32 [128][132] @36864
constexpr int MISCL = 32768;
constexpr int WHIo  = 36864;
constexpr int WLOo  = 55296;
constexpr int BHIo  = 36864;
constexpr int BLOo  = 71680;
constexpr int AGGo  = 36864;
constexpr int XHI1  = 73728;
constexpr int MISCE = 110592;
constexpr int HP_ST = 132;
constexpr int SMEM_BYTES = 113664;

// W1^T hi|lo fp16, 256B rows (full K), written once per launch
__device__ __align__(16) unsigned char g_WT[65536];

__device__ __forceinline__ unsigned smem_u32(const void* p) {
    unsigned a;
    asm("{ .reg .u64 t; cvta.to.shared.u64 t, %1; cvt.u32.u64 %0, t; }" : "=r"(a) : "l"(p));
    return a;
}

#define LDSM4(r, addr) \
    asm volatile("ldmatrix.sync.aligned.m8n8.x4.shared.b16 {%0,%1,%2,%3}, [%4];" \
        : "=r"((r)[0]), "=r"((r)[1]), "=r"((r)[2]), "=r"((r)[3]) : "r"(addr))

#define LDSM4T(r, addr) \
    asm volatile("ldmatrix.sync.aligned.m8n8.x4.trans.shared.b16 {%0,%1,%2,%3}, [%4];" \
        : "=r"((r)[0]), "=r"((r)[1]), "=r"((r)[2]), "=r"((r)[3]) : "r"(addr))

#define MMA16816(c, a, b0, b1) \
    asm volatile("mma.sync.aligned.m16n8k16.row.col.f32.f16.f16.f32 " \
        "{%0,%1,%2,%3},{%4,%5,%6,%7},{%8,%9},{%0,%1,%2,%3};" \
        : "+f"((c)[0]), "+f"((c)[1]), "+f"((c)[2]), "+f"((c)[3]) \
        : "r"((a)[0]), "r"((a)[1]), "r"((a)[2]), "r"((a)[3]), "r"(b0), "r"(b1))

__device__ __forceinline__ unsigned pack_h2(float lo, float hi_) {
    unsigned r;
    asm("cvt.rn.f16x2.f32 %0, %1, %2;" : "=r"(r) : "f"(hi_), "f"(lo));
    return r;
}
__device__ __forceinline__ unsigned pack_hh(__half a, __half b) {
    return ((unsigned)__half_as_ushort(b) << 16) | (unsigned)__half_as_ushort(a);
}
// ATILE swizzled 16B-group index for (row d, group g)
__device__ __forceinline__ unsigned asw(unsigned g, unsigned d) {
    return (g & 8u) | ((g & 7u) ^ (d & 7u));
}

// ---------------- prep: W1^T -> fp16 hi/lo, 256B rows ----------------
__global__ void prep_W_kernel(const float* __restrict__ W1) {
    int i = blockIdx.x * 256 + threadIdx.x;
    int k = i >> 7, n = i & 127;              // W1[k][n] -> WT[n][k]
    float v = W1[k * 128 + n];
    __half hi = __float2half_rn(v);
    __half lo = __float2half_rn(v - __half2float(hi));
    unsigned off = (unsigned)n * 256u + (unsigned)k * 2u;
    *(__half*)(g_WT + off)          = hi;
    *(__half*)(g_WT + 32768u + off) = lo;
}

// ---------------- main fused kernel ----------------
extern __shared__ float S[];

__global__ void __launch_bounds__(256, 2) sagpool_fused_kernel(
    const float* __restrict__ x,
    const int*   __restrict__ esrc,
    const int*   __restrict__ edst,
    const float* __restrict__ b1,
    const float* __restrict__ Ws,
    const float* __restrict__ bs,
    const float* __restrict__ Wlin,
    const float* __restrict__ blin,
    float*       __restrict__ out)
{
    const int g = blockIdx.x;
    const int t = threadIdx.x;
    const int lane = t & 31;
    const int warp = t >> 5;

    char*  Sb     = (char*)S;
    float* AGG    = (float*)(Sb + AGGo);
    float* rinv   = (float*)(Sb + MISCE);
    float* b1s    = rinv + 128;
    float* wss    = b1s  + 128;
    float* uvec   = (float*)(Sb + MISCL);
    float* score  = uvec  + 128;
    float* wsel   = score + 128;
    float* pooled = wsel  + 128;
    float* part   = pooled + 128;            // 256 floats

    // ---- Phase A: upfront loads — edges (regs), x both chunks, W chunk 0 ----
    const int ebase = g * EPG;
    int sl[8], dl[8];
#pragma unroll
    for (int e = 0; e < 8; e++) {
        int ei = ebase + t + e * 256;
        sl[e] = esrc[ei] & (NPG - 1);
        dl[e] = edst[ei] & (NPG - 1);
    }
    const float* xg = x + (size_t)g * NPG * HID;
#pragma unroll 1
    for (int h = 0; h < 2; h++) {
        const unsigned xb = (unsigned)(h * XHI1);
#pragma unroll
        for (int i = 0; i < 8; i++) {
            int idx = t + i * 256;
            int row = idx >> 4, f4 = idx & 15;
            float4 v = *(const float4*)(xg + row * HID + h * 64 + f4 * 4);
            __half h0 = __float2half_rn(v.x), h1 = __float2half_rn(v.y);
            __half h2 = __float2half_rn(v.z), h3 = __float2half_rn(v.w);
            *(uint2*)(Sb + xb + row * 144 + f4 * 8) =
                make_uint2(pack_hh(h0, h1), pack_hh(h2, h3));
            *(uint2*)(Sb + xb + 18432 + row * 144 + f4 * 8) =
                make_uint2(pack_h2(v.x - __half2float(h0), v.y - __half2float(h1)),
                           pack_h2(v.z - __half2float(h2), v.w - __half2float(h3)));
        }
    }
    {   // W chunk 0
        int4* wh = (int4*)(Sb + WHIo);
        int4* wl = (int4*)(Sb + WLOo);
        for (int i = t; i < 1024; i += 256) {
            int row = i >> 3, c = i & 7;
            wh[row * 9 + c] = *(const int4*)(g_WT + row * 256 + c * 16);
            wl[row * 9 + c] = *(const int4*)(g_WT + 32768 + row * 256 + c * 16);
        }
    }
    if (t < 128) { b1s[t] = b1[t]; wss[t] = Ws[t]; }
    __syncthreads();

    // ---- Phase B: GEMM1 hp = x@W1 (fp16 3-term split); ATILE built between chunks ----
    const int m0 = (warp & 3) * 32;
    const int n0 = (warp >> 2) * 64;
    const unsigned q = (unsigned)lane >> 3, r8 = (unsigned)lane & 7;
    const unsigned qh = q >> 1;
    const unsigned SMB = smem_u32(S);

    const unsigned rowA  = (m0 + (q & 1) * 8 + r8) * 144 + (q >> 1) * 16;
    const unsigned rowBW = (n0 + ((q >> 1) & 1) * 8 + r8) * 144 + (q & 1) * 16;
    const unsigned bHiB = SMB + WHIo + rowBW;
    const unsigned bLoB = SMB + WLOo + rowBW;

    float acc[2][8][4];
#pragma unroll
    for (int mt = 0; mt < 2; mt++)
#pragma unroll
        for (int nt = 0; nt < 8; nt++)
#pragma unroll
            for (int i = 0; i < 4; i++) acc[mt][nt][i] = 0.f;

#pragma unroll 1
    for (int h = 0; h < 2; h++) {
        if (h == 1) {
            __syncthreads();                       // ch0 MMA reads done
            // zero ATILE (32KB over dead x0) + W chunk-1 restage
            {
                int4 z = make_int4(0, 0, 0, 0);
                int4* az = (int4*)Sb;
                for (int i = t; i < 2048; i += 256) az[i] = z;
                int4* wh = (int4*)(Sb + WHIo);
                int4* wl = (int4*)(Sb + WLOo);
                for (int i = t; i < 1024; i += 256) {
                    int row = i >> 3, c = i & 7;
                    wh[row * 9 + c] = *(const int4*)(g_WT + row * 256 + 128 + c * 16);
                    wl[row * 9 + c] = *(const int4*)(g_WT + 32768 + row * 256 + 128 + c * 16);
                }
            }
            __syncthreads();
            // scatter edges directly into fp16 ATILE (+1.0 each, exact)
            {
                const unsigned short one = 0x3C00;
#pragma unroll
                for (int e = 0; e < 8; e++) {
                    unsigned d = (unsigned)dl[e], s = (unsigned)sl[e];
                    unsigned addr = SMB + d * 256u + (asw(s >> 3, d) << 4) + (s & 7u) * 2u;
                    asm volatile("red.shared.add.noftz.f16 [%0], %1;"
                                 :: "r"(addr), "h"(one) : "memory");
                }
            }
            __syncthreads();                       // scatter visible before ch1+rinv
        }
        const unsigned aHi0 = SMB + (unsigned)(h * XHI1) + rowA;
        const unsigned aHi1 = aHi0 + 16 * 144;
        const unsigned aLo0 = aHi0 + 18432u;
        const unsigned aLo1 = aHi1 + 18432u;
#pragma unroll
        for (int kk = 0; kk < 4; kk++) {
            const unsigned ko = (unsigned)kk * 32u;
            unsigned ah0[4], ah1[4], al0[4], al1[4];
            LDSM4(ah0, aHi0 + ko);
            LDSM4(ah1, aHi1 + ko);
            LDSM4(al0, aLo0 + ko);
            LDSM4(al1, aLo1 + ko);
#pragma unroll
            for (int p = 0; p < 4; p++) {
                unsigned bh[4], bl[4];
                LDSM4(bh, bHiB + p * (16 * 144) + ko);
                LDSM4(bl, bLoB + p * (16 * 144) + ko);
                MMA16816(acc[0][2 * p],     ah0, bh[0], bh[1]);
                MMA16816(acc[0][2 * p + 1], ah0, bh[2], bh[3]);
                MMA16816(acc[1][2 * p],     ah1, bh[0], bh[1]);
                MMA16816(acc[1][2 * p + 1], ah1, bh[2], bh[3]);
                MMA16816(acc[0][2 * p],     al0, bh[0], bh[1]);
                MMA16816(acc[0][2 * p + 1], al0, bh[2], bh[3]);
                MMA16816(acc[1][2 * p],     al1, bh[0], bh[1]);
                MMA16816(acc[1][2 * p + 1], al1, bh[2], bh[3]);
                MMA16816(acc[0][2 * p],     ah0, bl[0], bl[1]);
                MMA16816(acc[0][2 * p + 1], ah0, bl[2], bl[3]);
                MMA16816(acc[1][2 * p],     ah1, bl[0], bl[1]);
                MMA16816(acc[1][2 * p + 1], ah1, bl[2], bl[3]);
            }
        }
    }
    // degrees from fp16 row sums (+1 self loop); add self-loop to ATILE (own row only)
    if (t < 128) {
        const uint4* row = (const uint4*)(Sb + t * 256);
        __half2 s2 = __float2half2_rn(0.f);
#pragma unroll
        for (int gg = 0; gg < 16; gg++) {
            uint4 v = row[asw(gg, t)];
            s2 = __hadd2(s2, *(__half2*)&v.x);
            s2 = __hadd2(s2, *(__half2*)&v.y);
            s2 = __hadd2(s2, *(__half2*)&v.z);
            s2 = __hadd2(s2, *(__half2*)&v.w);
        }
        float deg = 1.f + __low2float(s2) + __high2float(s2);
        rinv[t] = rsqrtf(deg);
        __half* sp = (__half*)(Sb + t * 256 + (asw((unsigned)t >> 3, t) << 4) + (t & 7) * 2);
        *sp = __hadd(*sp, __float2half_rn(1.f));   // ATILE = N + I
    }
    __syncthreads();   // GEMM1 reads done + rinv/ATILE visible

    // ---- Phase C: hp' = rinv[s]*hp -> node-major [s][f] fp16 hi/lo, 272B rows ----
    {
        const int rb = lane >> 2, cb = 2 * (lane & 3);
#pragma unroll
        for (int mt = 0; mt < 2; mt++) {
            int row0 = m0 + 16 * mt + rb;
            float rv0 = rinv[row0], rv1 = rinv[row0 + 8];
#pragma unroll
            for (int nt = 0; nt < 8; nt++) {
                int col = n0 + 8 * nt + cb;
                float v0 = acc[mt][nt][0] * rv0, v1 = acc[mt][nt][1] * rv0;
                float v2 = acc[mt][nt][2] * rv1, v3 = acc[mt][nt][3] * rv1;
                __half h0 = __float2half_rn(v0), h1 = __float2half_rn(v1);
                __half h2 = __float2half_rn(v2), h3 = __float2half_rn(v3);
                unsigned o0 = row0 * 272u + col * 2u;
                unsigned o1 = (row0 + 8) * 272u + col * 2u;
                *(unsigned*)(Sb + BHIo + o0) = pack_hh(h0, h1);
                *(unsigned*)(Sb + BHIo + o1) = pack_hh(h2, h3);
                *(unsigned*)(Sb + BLOo + o0) =
                    pack_h2(v0 - __half2float(h0), v1 - __half2float(h1));
                *(unsigned*)(Sb + BLOo + o1) =
                    pack_h2(v2 - __half2float(h2), v3 - __half2float(h3));
            }
        }
    }
    __syncthreads();

    // ---- Phase E: GEMM2 = (N+I) @ hp' — after rinv[d] epilogue scale this is
    //      exactly the GCN aggregate (diagonal supplies the self-loop term) ----
    const unsigned rA0 = (unsigned)(m0 + (q & 1) * 8 + r8);
    const unsigned rA1 = rA0 + 16;
    const unsigned bT = ((q & 1) * 8 + r8) * 272u + (unsigned)(n0 + ((q >> 1) & 1) * 8) * 2u;
    const unsigned bH2 = SMB + BHIo + bT;
    const unsigned bL2 = SMB + BLOo + bT;

    float acc2[2][8][4];
#pragma unroll
    for (int mt = 0; mt < 2; mt++)
#pragma unroll
        for (int nt = 0; nt < 8; nt++)
#pragma unroll
            for (int i = 0; i < 4; i++) acc2[mt][nt][i] = 0.f;

#pragma unroll
    for (int kk = 0; kk < 8; kk++) {
        const unsigned gA = (unsigned)(kk * 2) + qh;
        const unsigned addrA0 = SMB + rA0 * 256 + (asw(gA, rA0) << 4);
        const unsigned addrA1 = SMB + rA1 * 256 + (asw(gA, rA1) << 4);
        const unsigned bko = (unsigned)(kk * 16 * 272);
        unsigned a0[4], a1[4];
        LDSM4(a0, addrA0);
        LDSM4(a1, addrA1);
#pragma unroll
        for (int p = 0; p < 4; p++) {
            unsigned bh[4], bl[4];
            LDSM4T(bh, bH2 + bko + p * 32);
            LDSM4T(bl, bL2 + bko + p * 32);
            MMA16816(acc2[0][2 * p],     a0, bh[0], bh[1]);
            MMA16816(acc2[0][2 * p + 1], a0, bh[2], bh[3]);
            MMA16816(acc2[1][2 * p],     a1, bh[0], bh[1]);
            MMA16816(acc2[1][2 * p + 1], a1, bh[2], bh[3]);
            MMA16816(acc2[0][2 * p],     a0, bl[0], bl[1]);
            MMA16816(acc2[0][2 * p + 1], a0, bl[2], bl[3]);
            MMA16816(acc2[1][2 * p],     a1, bl[0], bl[1]);
            MMA16816(acc2[1][2 * p + 1], a1, bl[2], bl[3]);
        }
    }
    __syncthreads();   // GEMM2 reads done -> B tiles dead, AGG may be written

    // ---- Phase F: epilogue AGG = relu(rinv[d]*D + b1)  +  fused score GEMV ----
    {
        const int rb = lane >> 2, cb = 2 * (lane & 3);
        float tg[4] = {0.f, 0.f, 0.f, 0.f};     // rows m0+rb, m0+8+rb, m0+16+rb, m0+24+rb
#pragma unroll
        for (int mt = 0; mt < 2; mt++) {
            int row0 = m0 + 16 * mt + rb;
            float rv0 = rinv[row0], rv1 = rinv[row0 + 8];
#pragma unroll
            for (int nt = 0; nt < 8; nt++) {
                int col = n0 + 8 * nt + cb;
                float bb0 = b1s[col], bb1 = b1s[col + 1];
                float w0 = wss[col], w1 = wss[col + 1];
                float v0 = fmaxf(fmaf(rv0, acc2[mt][nt][0], bb0), 0.f);
                float v1 = fmaxf(fmaf(rv0, acc2[mt][nt][1], bb1), 0.f);
                float v2 = fmaxf(fmaf(rv1, acc2[mt][nt][2], bb0), 0.f);
                float v3 = fmaxf(fmaf(rv1, acc2[mt][nt][3], bb1), 0.f);
                *(float2*)(AGG + row0 * HP_ST + col)       = make_float2(v0, v1);
                *(float2*)(AGG + (row0 + 8) * HP_ST + col) = make_float2(v2, v3);
                tg[mt * 2]     = fmaf(v0, w0, fmaf(v1, w1, tg[mt * 2]));
                tg[mt * 2 + 1] = fmaf(v2, w0, fmaf(v3, w1, tg[mt * 2 + 1]));
            }
        }
        // quad reduce (lanes sharing rb)
#pragma unroll
        for (int o = 1; o <= 2; o <<= 1) {
#pragma unroll
            for (int i = 0; i < 4; i++)
                tg[i] += __shfl_xor_sync(0xFFFFFFFFu, tg[i], o);
        }
        if ((lane & 3) == 0) {
            int half = (warp >> 2) * 128;
            part[half + m0 + rb]      = tg[0];
            part[half + m0 + 8 + rb]  = tg[1];
            part[half + m0 + 16 + rb] = tg[2];
            part[half + m0 + 24 + rb] = tg[3];
        }
    }
    __syncthreads();
    if (t < 128) uvec[t] = rinv[t] * (part[t] + part[t + 128]);
    __syncthreads();

    // ---- Phase H: score[d] = rinv[d]*<ATILE[d], uvec> + bs (diag absorbs self term) ----
    {
        int d = t & 127, hf = t >> 7;
        const char* rowb = Sb + d * 256;
        float a = 0.f;
#pragma unroll
        for (int j = 0; j < 8; j++) {
            int jj = (j + (d >> 3)) & 7;
            int gg = hf * 8 + jj;
            uint4 v = *(const uint4*)(rowb + (asw((unsigned)gg, (unsigned)d) << 4));
            const float* uv = uvec + gg * 8;
            float2 c0 = __half22float2(*(__half2*)&v.x);
            float2 c1 = __half22float2(*(__half2*)&v.y);
            float2 c2 = __half22float2(*(__half2*)&v.z);
            float2 c3 = __half22float2(*(__half2*)&v.w);
            a = fmaf(c0.x, uv[0], a); a = fmaf(c0.y, uv[1], a);
            a = fmaf(c1.x, uv[2], a); a = fmaf(c1.y, uv[3], a);
            a = fmaf(c2.x, uv[4], a); a = fmaf(c2.y, uv[5], a);
            a = fmaf(c3.x, uv[6], a); a = fmaf(c3.y, uv[7], a);
        }
        part[t] = a;
    }
    __syncthreads();
    if (t < 128)
        score[t] = rinv[t] * (part[t] + part[t + 128]) + bs[0];
    __syncthreads();

    // ---- Phase I: top-K rank (lax.top_k tie-break), 2 threads per row ----
    {
        int d = t & 127, hf = t >> 7;
        float sd = score[d];
        int rank = 0;
        const float4* sc4 = (const float4*)score + hf * 16;
#pragma unroll
        for (int j4 = 0; j4 < 16; j4++) {
            float4 s4 = sc4[j4];
            int j = (hf * 16 + j4) * 4;
            rank += (s4.x > sd) || (s4.x == sd && j     < d);
            rank += (s4.y > sd) || (s4.y == sd && j + 1 < d);
            rank += (s4.z > sd) || (s4.z == sd && j + 2 < d);
            rank += (s4.w > sd) || (s4.w == sd && j + 3 < d);
        }
        part[t] = (float)rank;
    }
    __syncthreads();
    if (t < 128) {
        int rank = (int)(part[t] + part[t + 128]);
        wsel[t] = (rank < KSEL) ? (tanhf(score[t]) * (1.0f / KSEL)) : 0.0f;
    }
    __syncthreads();

    // ---- Phase J: pooled[f] = sum_d wsel[d]*AGG[d][f], 2 threads per f ----
    {
        int f = t & 127, hf = t >> 7;
        const float* base = AGG + hf * 64 * HP_ST + f;
        const float* wsb  = wsel + hf * 64;
        float p = 0.f;
#pragma unroll 8
        for (int d = 0; d < 64; d++) p = fmaf(wsb[d], base[d * HP_ST], p);
        part[t] = p;
    }
    __syncthreads();
    if (t < 128) pooled[t] = part[t] + part[t + 128];
    __syncthreads();

    // ---- Phase K: out = pooled @ Wlin + blin, 2 threads per f ----
    {
        int f = t & 127, hf = t >> 7;
        const float* pl = pooled + hf * 64;
        const float* wl = Wlin + hf * 64 * 128 + f;
        float o = 0.f;
#pragma unroll 16
        for (int k = 0; k < 64; k++) o = fmaf(pl[k], wl[k * 128], o);
        part[t] = o;
    }
    __syncthreads();
    if (t < 128)
        out[(size_t)g * HID + t] = part[t] + part[t + 128] + blin[t];
}

extern "C" void kernel_launch(void* const* d_in, const int* in_sizes, int n_in,
                              void* d_out, int out_size) {
    const float* x    = (const float*)d_in[0];
    const int*   ei   = (const int*)  d_in[1];
    const float* W1   = (const float*)d_in[3];
    const float* b1   = (const float*)d_in[4];
    const float* Ws   = (const float*)d_in[5];
    const float* bs   = (const float*)d_in[6];
    const float* Wlin = (const float*)d_in[7];
    const float* blin = (const float*)d_in[8];
    float* out = (float*)d_out;

    const int E = in_sizes[1] / 2;
    const int* esrc = ei;
    const int* edst = ei + E;

    prep_W_kernel<<<64, 256>>>(W1);

    cudaFuncSetAttribute(sagpool_fused_kernel,
                         cudaFuncAttributeMaxDynamicSharedMemorySize, SMEM_BYTES);
    sagpool_fused_kernel<<<NB, 256, SMEM_BYTES>>>(
        x, esrc, edst, b1, Ws, bs, Wlin, blin, out);
}

// round 13
// speedup vs baseline: 2.4646x; 1.0055x over previous
#include <cuda_runtime.h>
#include <cuda_fp16.h>
#include <cstdint>
#include <stdint.h>
#include <math.h>

#define NB    512
#define NPG   128
#define EPG   2048
#define HID   128
#define KSEL  64

// ---- smem byte map (113,664 B, 2 CTAs/SM) ----
// Phase A / GEMM1: x0 hi@0 lo@18432 | W hi@36864 lo@55296 | x1 hi@73728 lo@92160
// mid-GEMM1 (x0 dead): ATILE fp16 [128][256B swizzled] @0 (32KB) -- scatter target
// post-GEMM1: B tiles BHI@36864 BLO@71680 (272B rows); misc-late @32768
// post-GEMM2: B-tile region dead -> part2/pooled @36864
constexpr int MISCL = 32768;
constexpr int WHIo  = 36864;
constexpr int WLOo  = 55296;
constexpr int BHIo  = 36864;
constexpr int BLOo  = 71680;
constexpr int XHI1  = 73728;
constexpr int MISCE = 110592;
constexpr int SMEM_BYTES = 113664;

// W1^T hi|lo fp16, 256B rows (full K), written once per launch
__device__ __align__(16) unsigned char g_WT[65536];

__device__ __forceinline__ unsigned smem_u32(const void* p) {
    unsigned a;
    asm("{ .reg .u64 t; cvta.to.shared.u64 t, %1; cvt.u32.u64 %0, t; }" : "=r"(a) : "l"(p));
    return a;
}

#define LDSM4(r, addr) \
    asm volatile("ldmatrix.sync.aligned.m8n8.x4.shared.b16 {%0,%1,%2,%3}, [%4];" \
        : "=r"((r)[0]), "=r"((r)[1]), "=r"((r)[2]), "=r"((r)[3]) : "r"(addr))

#define LDSM4T(r, addr) \
    asm volatile("ldmatrix.sync.aligned.m8n8.x4.trans.shared.b16 {%0,%1,%2,%3}, [%4];" \
        : "=r"((r)[0]), "=r"((r)[1]), "=r"((r)[2]), "=r"((r)[3]) : "r"(addr))

#define MMA16816(c, a, b0, b1) \
    asm volatile("mma.sync.aligned.m16n8k16.row.col.f32.f16.f16.f32 " \
        "{%0,%1,%2,%3},{%4,%5,%6,%7},{%8,%9},{%0,%1,%2,%3};" \
        : "+f"((c)[0]), "+f"((c)[1]), "+f"((c)[2]), "+f"((c)[3]) \
        : "r"((a)[0]), "r"((a)[1]), "r"((a)[2]), "r"((a)[3]), "r"(b0), "r"(b1))

__device__ __forceinline__ unsigned pack_h2(float lo, float hi_) {
    unsigned r;
    asm("cvt.rn.f16x2.f32 %0, %1, %2;" : "=r"(r) : "f"(hi_), "f"(lo));
    return r;
}
__device__ __forceinline__ unsigned pack_hh(__half a, __half b) {
    return ((unsigned)__half_as_ushort(b) << 16) | (unsigned)__half_as_ushort(a);
}
// ATILE swizzled 16B-group index for (row d, group g)
__device__ __forceinline__ unsigned asw(unsigned g, unsigned d) {
    return (g & 8u) | ((g & 7u) ^ (d & 7u));
}

// ---------------- prep: W1^T -> fp16 hi/lo, 256B rows ----------------
__global__ void prep_W_kernel(const float* __restrict__ W1) {
    int i = blockIdx.x * 256 + threadIdx.x;
    int k = i >> 7, n = i & 127;              // W1[k][n] -> WT[n][k]
    float v = W1[k * 128 + n];
    __half hi = __float2half_rn(v);
    __half lo = __float2half_rn(v - __half2float(hi));
    unsigned off = (unsigned)n * 256u + (unsigned)k * 2u;
    *(__half*)(g_WT + off)          = hi;
    *(__half*)(g_WT + 32768u + off) = lo;
}

// ---------------- main fused kernel ----------------
extern __shared__ float S[];

__global__ void __launch_bounds__(256, 2) sagpool_fused_kernel(
    const float* __restrict__ x,
    const int*   __restrict__ esrc,
    const int*   __restrict__ edst,
    const float* __restrict__ b1,
    const float* __restrict__ Ws,
    const float* __restrict__ bs,
    const float* __restrict__ Wlin,
    const float* __restrict__ blin,
    float*       __restrict__ out)
{
    const int g = blockIdx.x;
    const int t = threadIdx.x;
    const int lane = t & 31;
    const int warp = t >> 5;

    char*  Sb     = (char*)S;
    float* rinv   = (float*)(Sb + MISCE);
    float* b1s    = rinv + 128;
    float* wss    = b1s  + 128;
    float* uvec   = (float*)(Sb + MISCL);
    float* score  = uvec  + 128;
    float* wsel   = score + 128;
    float* part   = wsel + 128;              // 256 floats
    float* part2  = (float*)(Sb + BHIo);     // 512 floats (dead B-tile region)
    float* pooled = part2 + 512;

    // ---- Phase A: upfront loads — edges (regs), x both chunks, W chunk 0 ----
    const int ebase = g * EPG;
    int sl[8], dl[8];
#pragma unroll
    for (int e = 0; e < 8; e++) {
        int ei = ebase + t + e * 256;
        sl[e] = esrc[ei] & (NPG - 1);
        dl[e] = edst[ei] & (NPG - 1);
    }
    const float* xg = x + (size_t)g * NPG * HID;
#pragma unroll 1
    for (int h = 0; h < 2; h++) {
        const unsigned xb = (unsigned)(h * XHI1);
#pragma unroll
        for (int i = 0; i < 8; i++) {
            int idx = t + i * 256;
            int row = idx >> 4, f4 = idx & 15;
            float4 v = *(const float4*)(xg + row * HID + h * 64 + f4 * 4);
            __half h0 = __float2half_rn(v.x), h1 = __float2half_rn(v.y);
            __half h2 = __float2half_rn(v.z), h3 = __float2half_rn(v.w);
            *(uint2*)(Sb + xb + row * 144 + f4 * 8) =
                make_uint2(pack_hh(h0, h1), pack_hh(h2, h3));
            *(uint2*)(Sb + xb + 18432 + row * 144 + f4 * 8) =
                make_uint2(pack_h2(v.x - __half2float(h0), v.y - __half2float(h1)),
                           pack_h2(v.z - __half2float(h2), v.w - __half2float(h3)));
        }
    }
    {   // W chunk 0
        int4* wh = (int4*)(Sb + WHIo);
        int4* wl = (int4*)(Sb + WLOo);
        for (int i = t; i < 1024; i += 256) {
            int row = i >> 3, c = i & 7;
            wh[row * 9 + c] = *(const int4*)(g_WT + row * 256 + c * 16);
            wl[row * 9 + c] = *(const int4*)(g_WT + 32768 + row * 256 + c * 16);
        }
    }
    if (t < 128) { b1s[t] = b1[t]; wss[t] = Ws[t]; }
    __syncthreads();

    // ---- Phase B: GEMM1 hp = x@W1 (fp16 3-term split); ATILE built between chunks ----
    const int m0 = (warp & 3) * 32;
    const int n0 = (warp >> 2) * 64;
    const unsigned q = (unsigned)lane >> 3, r8 = (unsigned)lane & 7;
    const unsigned qh = q >> 1;
    const unsigned SMB = smem_u32(S);

    const unsigned rowA  = (m0 + (q & 1) * 8 + r8) * 144 + (q >> 1) * 16;
    const unsigned rowBW = (n0 + ((q >> 1) & 1) * 8 + r8) * 144 + (q & 1) * 16;
    const unsigned bHiB = SMB + WHIo + rowBW;
    const unsigned bLoB = SMB + WLOo + rowBW;

    float acc[2][8][4];
#pragma unroll
    for (int mt = 0; mt < 2; mt++)
#pragma unroll
        for (int nt = 0; nt < 8; nt++)
#pragma unroll
            for (int i = 0; i < 4; i++) acc[mt][nt][i] = 0.f;

#pragma unroll 1
    for (int h = 0; h < 2; h++) {
        if (h == 1) {
            __syncthreads();                       // ch0 MMA reads done
            {
                int4 z = make_int4(0, 0, 0, 0);
                int4* az = (int4*)Sb;
                for (int i = t; i < 2048; i += 256) az[i] = z;
                int4* wh = (int4*)(Sb + WHIo);
                int4* wl = (int4*)(Sb + WLOo);
                for (int i = t; i < 1024; i += 256) {
                    int row = i >> 3, c = i & 7;
                    wh[row * 9 + c] = *(const int4*)(g_WT + row * 256 + 128 + c * 16);
                    wl[row * 9 + c] = *(const int4*)(g_WT + 32768 + row * 256 + 128 + c * 16);
                }
            }
            __syncthreads();
            // scatter edges directly into fp16 ATILE (+1.0 each, exact)
            {
                const unsigned short one = 0x3C00;
#pragma unroll
                for (int e = 0; e < 8; e++) {
                    unsigned d = (unsigned)dl[e], s = (unsigned)sl[e];
                    unsigned addr = SMB + d * 256u + (asw(s >> 3, d) << 4) + (s & 7u) * 2u;
                    asm volatile("red.shared.add.noftz.f16 [%0], %1;"
                                 :: "r"(addr), "h"(one) : "memory");
                }
            }
            __syncthreads();                       // scatter visible before ch1+rinv
        }
        const unsigned aHi0 = SMB + (unsigned)(h * XHI1) + rowA;
        const unsigned aHi1 = aHi0 + 16 * 144;
        const unsigned aLo0 = aHi0 + 18432u;
        const unsigned aLo1 = aHi1 + 18432u;
#pragma unroll
        for (int kk = 0; kk < 4; kk++) {
            const unsigned ko = (unsigned)kk * 32u;
            unsigned ah0[4], ah1[4], al0[4], al1[4];
            LDSM4(ah0, aHi0 + ko);
            LDSM4(ah1, aHi1 + ko);
            LDSM4(al0, aLo0 + ko);
            LDSM4(al1, aLo1 + ko);
#pragma unroll
            for (int p = 0; p < 4; p++) {
                unsigned bh[4], bl[4];
                LDSM4(bh, bHiB + p * (16 * 144) + ko);
                LDSM4(bl, bLoB + p * (16 * 144) + ko);
                MMA16816(acc[0][2 * p],     ah0, bh[0], bh[1]);
                MMA16816(acc[0][2 * p + 1], ah0, bh[2], bh[3]);
                MMA16816(acc[1][2 * p],     ah1, bh[0], bh[1]);
                MMA16816(acc[1][2 * p + 1], ah1, bh[2], bh[3]);
                MMA16816(acc[0][2 * p],     al0, bh[0], bh[1]);
                MMA16816(acc[0][2 * p + 1], al0, bh[2], bh[3]);
                MMA16816(acc[1][2 * p],     al1, bh[0], bh[1]);
                MMA16816(acc[1][2 * p + 1], al1, bh[2], bh[3]);
                MMA16816(acc[0][2 * p],     ah0, bl[0], bl[1]);
                MMA16816(acc[0][2 * p + 1], ah0, bl[2], bl[3]);
                MMA16816(acc[1][2 * p],     ah1, bl[0], bl[1]);
                MMA16816(acc[1][2 * p + 1], ah1, bl[2], bl[3]);
            }
        }
    }
    // degrees from fp16 row sums (+1 self loop); add self-loop to ATILE (own row only)
    if (t < 128) {
        const uint4* row = (const uint4*)(Sb + t * 256);
        __half2 s2 = __float2half2_rn(0.f);
#pragma unroll
        for (int gg = 0; gg < 16; gg++) {
            uint4 v = row[asw(gg, t)];
            s2 = __hadd2(s2, *(__half2*)&v.x);
            s2 = __hadd2(s2, *(__half2*)&v.y);
            s2 = __hadd2(s2, *(__half2*)&v.z);
            s2 = __hadd2(s2, *(__half2*)&v.w);
        }
        float deg = 1.f + __low2float(s2) + __high2float(s2);
        rinv[t] = rsqrtf(deg);
        __half* sp = (__half*)(Sb + t * 256 + (asw((unsigned)t >> 3, t) << 4) + (t & 7) * 2);
        *sp = __hadd(*sp, __float2half_rn(1.f));   // ATILE = N + I
    }
    __syncthreads();   // GEMM1 reads done + rinv/ATILE visible

    // ---- Phase C: hp' = rinv[s]*hp -> node-major [s][f] fp16 hi/lo, 272B rows ----
    {
        const int rb = lane >> 2, cb = 2 * (lane & 3);
#pragma unroll
        for (int mt = 0; mt < 2; mt++) {
            int row0 = m0 + 16 * mt + rb;
            float rv0 = rinv[row0], rv1 = rinv[row0 + 8];
#pragma unroll
            for (int nt = 0; nt < 8; nt++) {
                int col = n0 + 8 * nt + cb;
                float v0 = acc[mt][nt][0] * rv0, v1 = acc[mt][nt][1] * rv0;
                float v2 = acc[mt][nt][2] * rv1, v3 = acc[mt][nt][3] * rv1;
                __half h0 = __float2half_rn(v0), h1 = __float2half_rn(v1);
                __half h2 = __float2half_rn(v2), h3 = __float2half_rn(v3);
                unsigned o0 = row0 * 272u + col * 2u;
                unsigned o1 = (row0 + 8) * 272u + col * 2u;
                *(unsigned*)(Sb + BHIo + o0) = pack_hh(h0, h1);
                *(unsigned*)(Sb + BHIo + o1) = pack_hh(h2, h3);
                *(unsigned*)(Sb + BLOo + o0) =
                    pack_h2(v0 - __half2float(h0), v1 - __half2float(h1));
                *(unsigned*)(Sb + BLOo + o1) =
                    pack_h2(v2 - __half2float(h2), v3 - __half2float(h3));
            }
        }
    }
    __syncthreads();

    // ---- Phase E: GEMM2 = (N+I) @ hp' — after rinv[d] epilogue scale this is
    //      exactly the GCN aggregate (diagonal supplies the self-loop term) ----
    const unsigned rA0 = (unsigned)(m0 + (q & 1) * 8 + r8);
    const unsigned rA1 = rA0 + 16;
    const unsigned bT = ((q & 1) * 8 + r8) * 272u + (unsigned)(n0 + ((q >> 1) & 1) * 8) * 2u;
    const unsigned bH2 = SMB + BHIo + bT;
    const unsigned bL2 = SMB + BLOo + bT;

    float acc2[2][8][4];
#pragma unroll
    for (int mt = 0; mt < 2; mt++)
#pragma unroll
        for (int nt = 0; nt < 8; nt++)
#pragma unroll
            for (int i = 0; i < 4; i++) acc2[mt][nt][i] = 0.f;

#pragma unroll
    for (int kk = 0; kk < 8; kk++) {
        const unsigned gA = (unsigned)(kk * 2) + qh;
        const unsigned addrA0 = SMB + rA0 * 256 + (asw(gA, rA0) << 4);
        const unsigned addrA1 = SMB + rA1 * 256 + (asw(gA, rA1) << 4);
        const unsigned bko = (unsigned)(kk * 16 * 272);
        unsigned a0[4], a1[4];
        LDSM4(a0, addrA0);
        LDSM4(a1, addrA1);
#pragma unroll
        for (int p = 0; p < 4; p++) {
            unsigned bh[4], bl[4];
            LDSM4T(bh, bH2 + bko + p * 32);
            LDSM4T(bl, bL2 + bko + p * 32);
            MMA16816(acc2[0][2 * p],     a0, bh[0], bh[1]);
            MMA16816(acc2[0][2 * p + 1], a0, bh[2], bh[3]);
            MMA16816(acc2[1][2 * p],     a1, bh[0], bh[1]);
            MMA16816(acc2[1][2 * p + 1], a1, bh[2], bh[3]);
            MMA16816(acc2[0][2 * p],     a0, bl[0], bl[1]);
            MMA16816(acc2[0][2 * p + 1], a0, bl[2], bl[3]);
            MMA16816(acc2[1][2 * p],     a1, bl[0], bl[1]);
            MMA16816(acc2[1][2 * p + 1], a1, bl[2], bl[3]);
        }
    }
    __syncthreads();   // GEMM2 reads done -> B tiles dead (part2/pooled live there)

    // ---- Phase F: epilogue in registers: acc2 = relu(rinv[d]*D + b1) + fused score GEMV ----
    {
        const int rb = lane >> 2, cb = 2 * (lane & 3);
        float tg[4] = {0.f, 0.f, 0.f, 0.f};
#pragma unroll
        for (int mt = 0; mt < 2; mt++) {
            int row0 = m0 + 16 * mt + rb;
            float rv0 = rinv[row0], rv1 = rinv[row0 + 8];
#pragma unroll
            for (int nt = 0; nt < 8; nt++) {
                int col = n0 + 8 * nt + cb;
                float bb0 = b1s[col], bb1 = b1s[col + 1];
                float w0 = wss[col], w1 = wss[col + 1];
                float v0 = fmaxf(fmaf(rv0, acc2[mt][nt][0], bb0), 0.f);
                float v1 = fmaxf(fmaf(rv0, acc2[mt][nt][1], bb1), 0.f);
                float v2 = fmaxf(fmaf(rv1, acc2[mt][nt][2], bb0), 0.f);
                float v3 = fmaxf(fmaf(rv1, acc2[mt][nt][3], bb1), 0.f);
                acc2[mt][nt][0] = v0; acc2[mt][nt][1] = v1;
                acc2[mt][nt][2] = v2; acc2[mt][nt][3] = v3;
                tg[mt * 2]     = fmaf(v0, w0, fmaf(v1, w1, tg[mt * 2]));
                tg[mt * 2 + 1] = fmaf(v2, w0, fmaf(v3, w1, tg[mt * 2 + 1]));
            }
        }
#pragma unroll
        for (int o = 1; o <= 2; o <<= 1) {
#pragma unroll
            for (int i = 0; i < 4; i++)
                tg[i] += __shfl_xor_sync(0xFFFFFFFFu, tg[i], o);
        }
        if ((lane & 3) == 0) {
            int half = (warp >> 2) * 128;
            part[half + m0 + rb]      = tg[0];
            part[half + m0 + 8 + rb]  = tg[1];
            part[half + m0 + 16 + rb] = tg[2];
            part[half + m0 + 24 + rb] = tg[3];
        }
    }
    __syncthreads();
    if (t < 128) uvec[t] = rinv[t] * (part[t] + part[t + 128]);
    __syncthreads();

    // ---- Phase H: score[d] = rinv[d]*<ATILE[d], uvec> + bs (diag absorbs self term) ----
    {
        int d = t & 127, hf = t >> 7;
        const char* rowb = Sb + d * 256;
        float a = 0.f;
#pragma unroll
        for (int j = 0; j < 8; j++) {
            int jj = (j + (d >> 3)) & 7;
            int gg = hf * 8 + jj;
            uint4 v = *(const uint4*)(rowb + (asw((unsigned)gg, (unsigned)d) << 4));
            const float* uv = uvec + gg * 8;
            float2 c0 = __half22float2(*(__half2*)&v.x);
            float2 c1 = __half22float2(*(__half2*)&v.y);
            float2 c2 = __half22float2(*(__half2*)&v.z);
            float2 c3 = __half22float2(*(__half2*)&v.w);
            a = fmaf(c0.x, uv[0], a); a = fmaf(c0.y, uv[1], a);
            a = fmaf(c1.x, uv[2], a); a = fmaf(c1.y, uv[3], a);
            a = fmaf(c2.x, uv[4], a); a = fmaf(c2.y, uv[5], a);
            a = fmaf(c3.x, uv[6], a); a = fmaf(c3.y, uv[7], a);
        }
        part[t] = a;
    }
    __syncthreads();
    if (t < 128)
        score[t] = rinv[t] * (part[t] + part[t + 128]) + bs[0];
    __syncthreads();

    // ---- Phase I: top-K rank (lax.top_k tie-break), 2 threads per row ----
    {
        int d = t & 127, hf = t >> 7;
        float sd = score[d];
        int rank = 0;
        const float4* sc4 = (const float4*)score + hf * 16;
#pragma unroll
        for (int j4 = 0; j4 < 16; j4++) {
            float4 s4 = sc4[j4];
            int j = (hf * 16 + j4) * 4;
            rank += (s4.x > sd) || (s4.x == sd && j     < d);
            rank += (s4.y > sd) || (s4.y == sd && j + 1 < d);
            rank += (s4.z > sd) || (s4.z == sd && j + 2 < d);
            rank += (s4.w > sd) || (s4.w == sd && j + 3 < d);
        }
        part[t] = (float)rank;
    }
    __syncthreads();
    if (t < 128) {
        int rank = (int)(part[t] + part[t + 128]);
        wsel[t] = (rank < KSEL) ? (tanhf(score[t]) * (1.0f / KSEL)) : 0.0f;
    }
    __syncthreads();

    // ---- Phase J: pooled partials from registers (acc2 holds relu'd h) ----
    {
        const int rb = lane >> 2, cb = 2 * (lane & 3);
        float pp[8][2];
#pragma unroll
        for (int nt = 0; nt < 8; nt++) { pp[nt][0] = 0.f; pp[nt][1] = 0.f; }
#pragma unroll
        for (int mt = 0; mt < 2; mt++) {
            int row0 = m0 + 16 * mt + rb;
            float w0 = wsel[row0], w1 = wsel[row0 + 8];
#pragma unroll
            for (int nt = 0; nt < 8; nt++) {
                pp[nt][0] = fmaf(w0, acc2[mt][nt][0], fmaf(w1, acc2[mt][nt][2], pp[nt][0]));
                pp[nt][1] = fmaf(w0, acc2[mt][nt][1], fmaf(w1, acc2[mt][nt][3], pp[nt][1]));
            }
        }
        // reduce across the 8 lanes sharing the same columns (rb varies)
#pragma unroll
        for (int o = 4; o <= 16; o <<= 1) {
#pragma unroll
            for (int nt = 0; nt < 8; nt++) {
                pp[nt][0] += __shfl_xor_sync(0xFFFFFFFFu, pp[nt][0], o);
                pp[nt][1] += __shfl_xor_sync(0xFFFFFFFFu, pp[nt][1], o);
            }
        }
        if (lane < 4) {
            float* dst = part2 + (warp & 3) * 128;
#pragma unroll
            for (int nt = 0; nt < 8; nt++) {
                int col = n0 + 8 * nt + cb;
                dst[col]     = pp[nt][0];
                dst[col + 1] = pp[nt][1];
            }
        }
    }
    __syncthreads();
    if (t < 128)
        pooled[t] = part2[t] + part2[128 + t] + part2[256 + t] + part2[384 + t];
    __syncthreads();

    // ---- Phase K: out = pooled @ Wlin + blin, 2 threads per f ----
    {
        int f = t & 127, hf = t >> 7;
        const float* pl = pooled + hf * 64;
        const float* wl = Wlin + hf * 64 * 128 + f;
        float o = 0.f;
#pragma unroll 16
        for (int k = 0; k < 64; k++) o = fmaf(pl[k], wl[k * 128], o);
        part[t] = o;
    }
    __syncthreads();
    if (t < 128)
        out[(size_t)g * HID + t] = part[t] + part[t + 128] + blin[t];
}

extern "C" void kernel_launch(void* const* d_in, const int* in_sizes, int n_in,
                              void* d_out, int out_size) {
    const float* x    = (const float*)d_in[0];
    const int*   ei   = (const int*)  d_in[1];
    const float* W1   = (const float*)d_in[3];
    const float* b1   = (const float*)d_in[4];
    const float* Ws   = (const float*)d_in[5];
    const float* bs   = (const float*)d_in[6];
    const float* Wlin = (const float*)d_in[7];
    const float* blin = (const float*)d_in[8];
    float* out = (float*)d_out;

    const int E = in_sizes[1] / 2;
    const int* esrc = ei;
    const int* edst = ei + E;

    prep_W_kernel<<<64, 256>>>(W1);

    cudaFuncSetAttribute(sagpool_fused_kernel,
                         cudaFuncAttributeMaxDynamicSharedMemorySize, SMEM_BYTES);
    sagpool_fused_kernel<<<NB, 256, SMEM_BYTES>>>(
        x, esrc, edst, b1, Ws, bs, Wlin, blin, out);
}

// round 14
// speedup vs baseline: 2.7164x; 1.1022x over previous
#include <cuda_runtime.h>
#include <cuda_fp16.h>
#include <cstdint>
#include <stdint.h>
#include <math.h>

#define NB    512
#define NPG   128
#define EPG   2048
#define HID   128
#define KSEL  64

// ---- smem byte map (113,664 B, 2 CTAs/SM) ----
// Phase A / GEMM1: x0 hi@0 lo@18432 | W(chunk) hi@36864 lo@55296 (k-major 272B rows)
//                  | x1 hi@73728 lo@92160
// mid-GEMM1 (x0 dead): ATILE fp16 [128][256B swizzled] @0 (32KB) -- scatter target
// post-GEMM1: B tiles BHI@36864 BLO@71680 (272B rows); misc-late @32768
// post-GEMM2: B-tile region dead -> part2/pooled @36864
constexpr int MISCL = 32768;
constexpr int WHIo  = 36864;
constexpr int WLOo  = 55296;
constexpr int BHIo  = 36864;
constexpr int BLOo  = 71680;
constexpr int XHI1  = 73728;
constexpr int MISCE = 110592;
constexpr int SMEM_BYTES = 113664;

__device__ __forceinline__ unsigned smem_u32(const void* p) {
    unsigned a;
    asm("{ .reg .u64 t; cvta.to.shared.u64 t, %1; cvt.u32.u64 %0, t; }" : "=r"(a) : "l"(p));
    return a;
}

#define LDSM4(r, addr) \
    asm volatile("ldmatrix.sync.aligned.m8n8.x4.shared.b16 {%0,%1,%2,%3}, [%4];" \
        : "=r"((r)[0]), "=r"((r)[1]), "=r"((r)[2]), "=r"((r)[3]) : "r"(addr))

#define LDSM4T(r, addr) \
    asm volatile("ldmatrix.sync.aligned.m8n8.x4.trans.shared.b16 {%0,%1,%2,%3}, [%4];" \
        : "=r"((r)[0]), "=r"((r)[1]), "=r"((r)[2]), "=r"((r)[3]) : "r"(addr))

#define MMA16816(c, a, b0, b1) \
    asm volatile("mma.sync.aligned.m16n8k16.row.col.f32.f16.f16.f32 " \
        "{%0,%1,%2,%3},{%4,%5,%6,%7},{%8,%9},{%0,%1,%2,%3};" \
        : "+f"((c)[0]), "+f"((c)[1]), "+f"((c)[2]), "+f"((c)[3]) \
        : "r"((a)[0]), "r"((a)[1]), "r"((a)[2]), "r"((a)[3]), "r"(b0), "r"(b1))

__device__ __forceinline__ unsigned pack_h2(float lo, float hi_) {
    unsigned r;
    asm("cvt.rn.f16x2.f32 %0, %1, %2;" : "=r"(r) : "f"(hi_), "f"(lo));
    return r;
}
__device__ __forceinline__ unsigned pack_hh(__half a, __half b) {
    return ((unsigned)__half_as_ushort(b) << 16) | (unsigned)__half_as_ushort(a);
}
// ATILE swizzled 16B-group index for (row d, group g)
__device__ __forceinline__ unsigned asw(unsigned g, unsigned d) {
    return (g & 8u) | ((g & 7u) ^ (d & 7u));
}

// ---------------- main fused kernel (single launch) ----------------
extern __shared__ float S[];

__global__ void __launch_bounds__(256, 2) sagpool_fused_kernel(
    const float* __restrict__ x,
    const int*   __restrict__ esrc,
    const int*   __restrict__ edst,
    const float* __restrict__ W1,
    const float* __restrict__ b1,
    const float* __restrict__ Ws,
    const float* __restrict__ bs,
    const float* __restrict__ Wlin,
    const float* __restrict__ blin,
    float*       __restrict__ out)
{
    const int g = blockIdx.x;
    const int t = threadIdx.x;
    const int lane = t & 31;
    const int warp = t >> 5;

    char*  Sb     = (char*)S;
    float* rinv   = (float*)(Sb + MISCE);
    float* b1s    = rinv + 128;
    float* wss    = b1s  + 128;
    float* uvec   = (float*)(Sb + MISCL);
    float* score  = uvec  + 128;
    float* wsel   = score + 128;
    float* part   = wsel + 128;              // 256 floats
    float* part2  = (float*)(Sb + BHIo);     // 512 floats (dead B-tile region)
    float* pooled = part2 + 512;

    // ---- Phase A: upfront loads — edges (regs), x both chunks, W chunk 0 ----
    const int ebase = g * EPG;
    int sl[8], dl[8];
#pragma unroll
    for (int e = 0; e < 8; e++) {
        int ei = ebase + t + e * 256;
        sl[e] = esrc[ei] & (NPG - 1);
        dl[e] = edst[ei] & (NPG - 1);
    }
    const float* xg = x + (size_t)g * NPG * HID;
#pragma unroll 1
    for (int h = 0; h < 2; h++) {
        const unsigned xb = (unsigned)(h * XHI1);
#pragma unroll
        for (int i = 0; i < 8; i++) {
            int idx = t + i * 256;
            int row = idx >> 4, f4 = idx & 15;
            float4 v = *(const float4*)(xg + row * HID + h * 64 + f4 * 4);
            __half h0 = __float2half_rn(v.x), h1 = __float2half_rn(v.y);
            __half h2 = __float2half_rn(v.z), h3 = __float2half_rn(v.w);
            *(uint2*)(Sb + xb + row * 144 + f4 * 8) =
                make_uint2(pack_hh(h0, h1), pack_hh(h2, h3));
            *(uint2*)(Sb + xb + 18432 + row * 144 + f4 * 8) =
                make_uint2(pack_h2(v.x - __half2float(h0), v.y - __half2float(h1)),
                           pack_h2(v.z - __half2float(h2), v.w - __half2float(h3)));
        }
    }
    {   // W chunk 0: k-major [64 k][128 n], fp16 hi/lo, 272B rows (for ldmatrix.trans)
#pragma unroll
        for (int i = 0; i < 8; i++) {
            int idx4 = t + i * 256;            // 0..2047
            int k = idx4 >> 5, n4 = idx4 & 31;
            float4 v = *(const float4*)(W1 + k * 128 + n4 * 4);
            __half h0 = __float2half_rn(v.x), h1 = __float2half_rn(v.y);
            __half h2 = __float2half_rn(v.z), h3 = __float2half_rn(v.w);
            *(uint2*)(Sb + WHIo + k * 272 + n4 * 8) =
                make_uint2(pack_hh(h0, h1), pack_hh(h2, h3));
            *(uint2*)(Sb + WLOo + k * 272 + n4 * 8) =
                make_uint2(pack_h2(v.x - __half2float(h0), v.y - __half2float(h1)),
                           pack_h2(v.z - __half2float(h2), v.w - __half2float(h3)));
        }
    }
    if (t < 128) { b1s[t] = b1[t]; wss[t] = Ws[t]; }
    __syncthreads();

    // ---- Phase B: GEMM1 hp = x@W1 (fp16 3-term split); ATILE built between chunks ----
    const int m0 = (warp & 3) * 32;
    const int n0 = (warp >> 2) * 64;
    const unsigned q = (unsigned)lane >> 3, r8 = (unsigned)lane & 7;
    const unsigned qh = q >> 1;
    const unsigned SMB = smem_u32(S);

    const unsigned rowA = (m0 + (q & 1) * 8 + r8) * 144 + (q >> 1) * 16;
    // B (W, trans): row = k, col = n — mirrors GEMM2's hp' addressing
    const unsigned bTW = ((q & 1) * 8 + r8) * 272u + (unsigned)(n0 + ((q >> 1) & 1) * 8) * 2u;
    const unsigned bHiB = SMB + WHIo + bTW;
    const unsigned bLoB = SMB + WLOo + bTW;

    float acc[2][8][4];
#pragma unroll
    for (int mt = 0; mt < 2; mt++)
#pragma unroll
        for (int nt = 0; nt < 8; nt++)
#pragma unroll
            for (int i = 0; i < 4; i++) acc[mt][nt][i] = 0.f;

#pragma unroll 1
    for (int h = 0; h < 2; h++) {
        if (h == 1) {
            __syncthreads();                       // ch0 MMA reads done
            {
                int4 z = make_int4(0, 0, 0, 0);
                int4* az = (int4*)Sb;
                for (int i = t; i < 2048; i += 256) az[i] = z;
                // W chunk 1 restage (convert from W1 rows 64..127)
#pragma unroll
                for (int i = 0; i < 8; i++) {
                    int idx4 = t + i * 256;
                    int k = idx4 >> 5, n4 = idx4 & 31;
                    float4 v = *(const float4*)(W1 + (64 + k) * 128 + n4 * 4);
                    __half h0 = __float2half_rn(v.x), h1 = __float2half_rn(v.y);
                    __half h2 = __float2half_rn(v.z), h3 = __float2half_rn(v.w);
                    *(uint2*)(Sb + WHIo + k * 272 + n4 * 8) =
                        make_uint2(pack_hh(h0, h1), pack_hh(h2, h3));
                    *(uint2*)(Sb + WLOo + k * 272 + n4 * 8) =
                        make_uint2(pack_h2(v.x - __half2float(h0), v.y - __half2float(h1)),
                                   pack_h2(v.z - __half2float(h2), v.w - __half2float(h3)));
                }
            }
            __syncthreads();
            // scatter edges directly into fp16 ATILE (+1.0 each, exact)
            {
                const unsigned short one = 0x3C00;
#pragma unroll
                for (int e = 0; e < 8; e++) {
                    unsigned d = (unsigned)dl[e], s = (unsigned)sl[e];
                    unsigned addr = SMB + d * 256u + (asw(s >> 3, d) << 4) + (s & 7u) * 2u;
                    asm volatile("red.shared.add.noftz.f16 [%0], %1;"
                                 :: "r"(addr), "h"(one) : "memory");
                }
            }
            __syncthreads();                       // scatter visible before ch1+rinv
        }
        const unsigned aHi0 = SMB + (unsigned)(h * XHI1) + rowA;
        const unsigned aHi1 = aHi0 + 16 * 144;
        const unsigned aLo0 = aHi0 + 18432u;
        const unsigned aLo1 = aHi1 + 18432u;
#pragma unroll
        for (int kk = 0; kk < 4; kk++) {
            const unsigned ko  = (unsigned)kk * 32u;          // A byte offset (16 k elems)
            const unsigned bko = (unsigned)(kk * 16 * 272);   // B row offset (16 k rows)
            unsigned ah0[4], ah1[4], al0[4], al1[4];
            LDSM4(ah0, aHi0 + ko);
            LDSM4(ah1, aHi1 + ko);
            LDSM4(al0, aLo0 + ko);
            LDSM4(al1, aLo1 + ko);
#pragma unroll
            for (int p = 0; p < 4; p++) {
                unsigned bh[4], bl[4];
                LDSM4T(bh, bHiB + bko + p * 32);
                LDSM4T(bl, bLoB + bko + p * 32);
                MMA16816(acc[0][2 * p],     ah0, bh[0], bh[1]);
                MMA16816(acc[0][2 * p + 1], ah0, bh[2], bh[3]);
                MMA16816(acc[1][2 * p],     ah1, bh[0], bh[1]);
                MMA16816(acc[1][2 * p + 1], ah1, bh[2], bh[3]);
                MMA16816(acc[0][2 * p],     al0, bh[0], bh[1]);
                MMA16816(acc[0][2 * p + 1], al0, bh[2], bh[3]);
                MMA16816(acc[1][2 * p],     al1, bh[0], bh[1]);
                MMA16816(acc[1][2 * p + 1], al1, bh[2], bh[3]);
                MMA16816(acc[0][2 * p],     ah0, bl[0], bl[1]);
                MMA16816(acc[0][2 * p + 1], ah0, bl[2], bl[3]);
                MMA16816(acc[1][2 * p],     ah1, bl[0], bl[1]);
                MMA16816(acc[1][2 * p + 1], ah1, bl[2], bl[3]);
            }
        }
    }
    // degrees from fp16 row sums (+1 self loop); add self-loop to ATILE (own row only)
    if (t < 128) {
        const uint4* row = (const uint4*)(Sb + t * 256);
        __half2 s2 = __float2half2_rn(0.f);
#pragma unroll
        for (int gg = 0; gg < 16; gg++) {
            uint4 v = row[asw(gg, t)];
            s2 = __hadd2(s2, *(__half2*)&v.x);
            s2 = __hadd2(s2, *(__half2*)&v.y);
            s2 = __hadd2(s2, *(__half2*)&v.z);
            s2 = __hadd2(s2, *(__half2*)&v.w);
        }
        float deg = 1.f + __low2float(s2) + __high2float(s2);
        rinv[t] = rsqrtf(deg);
        __half* sp = (__half*)(Sb + t * 256 + (asw((unsigned)t >> 3, t) << 4) + (t & 7) * 2);
        *sp = __hadd(*sp, __float2half_rn(1.f));   // ATILE = N + I
    }
    __syncthreads();   // GEMM1 reads done + rinv/ATILE visible

    // ---- Phase C: hp' = rinv[s]*hp -> node-major [s][f] fp16 hi/lo, 272B rows ----
    {
        const int rb = lane >> 2, cb = 2 * (lane & 3);
#pragma unroll
        for (int mt = 0; mt < 2; mt++) {
            int row0 = m0 + 16 * mt + rb;
            float rv0 = rinv[row0], rv1 = rinv[row0 + 8];
#pragma unroll
            for (int nt = 0; nt < 8; nt++) {
                int col = n0 + 8 * nt + cb;
                float v0 = acc[mt][nt][0] * rv0, v1 = acc[mt][nt][1] * rv0;
                float v2 = acc[mt][nt][2] * rv1, v3 = acc[mt][nt][3] * rv1;
                __half h0 = __float2half_rn(v0), h1 = __float2half_rn(v1);
                __half h2 = __float2half_rn(v2), h3 = __float2half_rn(v3);
                unsigned o0 = row0 * 272u + col * 2u;
                unsigned o1 = (row0 + 8) * 272u + col * 2u;
                *(unsigned*)(Sb + BHIo + o0) = pack_hh(h0, h1);
                *(unsigned*)(Sb + BHIo + o1) = pack_hh(h2, h3);
                *(unsigned*)(Sb + BLOo + o0) =
                    pack_h2(v0 - __half2float(h0), v1 - __half2float(h1));
                *(unsigned*)(Sb + BLOo + o1) =
                    pack_h2(v2 - __half2float(h2), v3 - __half2float(h3));
            }
        }
    }
    __syncthreads();

    // ---- Phase E: GEMM2 = (N+I) @ hp' — after rinv[d] epilogue scale this is
    //      exactly the GCN aggregate (diagonal supplies the self-loop term) ----
    const unsigned rA0 = (unsigned)(m0 + (q & 1) * 8 + r8);
    const unsigned rA1 = rA0 + 16;
    const unsigned bT = ((q & 1) * 8 + r8) * 272u + (unsigned)(n0 + ((q >> 1) & 1) * 8) * 2u;
    const unsigned bH2 = SMB + BHIo + bT;
    const unsigned bL2 = SMB + BLOo + bT;

    float acc2[2][8][4];
#pragma unroll
    for (int mt = 0; mt < 2; mt++)
#pragma unroll
        for (int nt = 0; nt < 8; nt++)
#pragma unroll
            for (int i = 0; i < 4; i++) acc2[mt][nt][i] = 0.f;

#pragma unroll
    for (int kk = 0; kk < 8; kk++) {
        const unsigned gA = (unsigned)(kk * 2) + qh;
        const unsigned addrA0 = SMB + rA0 * 256 + (asw(gA, rA0) << 4);
        const unsigned addrA1 = SMB + rA1 * 256 + (asw(gA, rA1) << 4);
        const unsigned bko = (unsigned)(kk * 16 * 272);
        unsigned a0[4], a1[4];
        LDSM4(a0, addrA0);
        LDSM4(a1, addrA1);
#pragma unroll
        for (int p = 0; p < 4; p++) {
            unsigned bh[4], bl[4];
            LDSM4T(bh, bH2 + bko + p * 32);
            LDSM4T(bl, bL2 + bko + p * 32);
            MMA16816(acc2[0][2 * p],     a0, bh[0], bh[1]);
            MMA16816(acc2[0][2 * p + 1], a0, bh[2], bh[3]);
            MMA16816(acc2[1][2 * p],     a1, bh[0], bh[1]);
            MMA16816(acc2[1][2 * p + 1], a1, bh[2], bh[3]);
            MMA16816(acc2[0][2 * p],     a0, bl[0], bl[1]);
            MMA16816(acc2[0][2 * p + 1], a0, bl[2], bl[3]);
            MMA16816(acc2[1][2 * p],     a1, bl[0], bl[1]);
            MMA16816(acc2[1][2 * p + 1], a1, bl[2], bl[3]);
        }
    }
    __syncthreads();   // GEMM2 reads done -> B tiles dead (part2/pooled live there)

    // ---- Phase F: epilogue in registers: acc2 = relu(rinv[d]*D + b1) + fused score GEMV ----
    {
        const int rb = lane >> 2, cb = 2 * (lane & 3);
        float tg[4] = {0.f, 0.f, 0.f, 0.f};
#pragma unroll
        for (int mt = 0; mt < 2; mt++) {
            int row0 = m0 + 16 * mt + rb;
            float rv0 = rinv[row0], rv1 = rinv[row0 + 8];
#pragma unroll
            for (int nt = 0; nt < 8; nt++) {
                int col = n0 + 8 * nt + cb;
                float bb0 = b1s[col], bb1 = b1s[col + 1];
                float w0 = wss[col], w1 = wss[col + 1];
                float v0 = fmaxf(fmaf(rv0, acc2[mt][nt][0], bb0), 0.f);
                float v1 = fmaxf(fmaf(rv0, acc2[mt][nt][1], bb1), 0.f);
                float v2 = fmaxf(fmaf(rv1, acc2[mt][nt][2], bb0), 0.f);
                float v3 = fmaxf(fmaf(rv1, acc2[mt][nt][3], bb1), 0.f);
                acc2[mt][nt][0] = v0; acc2[mt][nt][1] = v1;
                acc2[mt][nt][2] = v2; acc2[mt][nt][3] = v3;
                tg[mt * 2]     = fmaf(v0, w0, fmaf(v1, w1, tg[mt * 2]));
                tg[mt * 2 + 1] = fmaf(v2, w0, fmaf(v3, w1, tg[mt * 2 + 1]));
            }
        }
#pragma unroll
        for (int o = 1; o <= 2; o <<= 1) {
#pragma unroll
            for (int i = 0; i < 4; i++)
                tg[i] += __shfl_xor_sync(0xFFFFFFFFu, tg[i], o);
        }
        if ((lane & 3) == 0) {
            int half = (warp >> 2) * 128;
            part[half + m0 + rb]      = tg[0];
            part[half + m0 + 8 + rb]  = tg[1];
            part[half + m0 + 16 + rb] = tg[2];
            part[half + m0 + 24 + rb] = tg[3];
        }
    }
    __syncthreads();
    if (t < 128) uvec[t] = rinv[t] * (part[t] + part[t + 128]);
    __syncthreads();

    // ---- Phase H: score[d] = rinv[d]*<ATILE[d], uvec> + bs (diag absorbs self term) ----
    {
        int d = t & 127, hf = t >> 7;
        const char* rowb = Sb + d * 256;
        float a = 0.f;
#pragma unroll
        for (int j = 0; j < 8; j++) {
            int jj = (j + (d >> 3)) & 7;
            int gg = hf * 8 + jj;
            uint4 v = *(const uint4*)(rowb + (asw((unsigned)gg, (unsigned)d) << 4));
            const float* uv = uvec + gg * 8;
            float2 c0 = __half22float2(*(__half2*)&v.x);
            float2 c1 = __half22float2(*(__half2*)&v.y);
            float2 c2 = __half22float2(*(__half2*)&v.z);
            float2 c3 = __half22float2(*(__half2*)&v.w);
            a = fmaf(c0.x, uv[0], a); a = fmaf(c0.y, uv[1], a);
            a = fmaf(c1.x, uv[2], a); a = fmaf(c1.y, uv[3], a);
            a = fmaf(c2.x, uv[4], a); a = fmaf(c2.y, uv[5], a);
            a = fmaf(c3.x, uv[6], a); a = fmaf(c3.y, uv[7], a);
        }
        part[t] = a;
    }
    __syncthreads();
    if (t < 128)
        score[t] = rinv[t] * (part[t] + part[t + 128]) + bs[0];
    __syncthreads();

    // ---- Phase I: top-K rank (lax.top_k tie-break), 2 threads per row ----
    {
        int d = t & 127, hf = t >> 7;
        float sd = score[d];
        int rank = 0;
        const float4* sc4 = (const float4*)score + hf * 16;
#pragma unroll
        for (int j4 = 0; j4 < 16; j4++) {
            float4 s4 = sc4[j4];
            int j = (hf * 16 + j4) * 4;
            rank += (s4.x > sd) || (s4.x == sd && j     < d);
            rank += (s4.y > sd) || (s4.y == sd && j + 1 < d);
            rank += (s4.z > sd) || (s4.z == sd && j + 2 < d);
            rank += (s4.w > sd) || (s4.w == sd && j + 3 < d);
        }
        part[t] = (float)rank;
    }
    __syncthreads();
    if (t < 128) {
        int rank = (int)(part[t] + part[t + 128]);
        wsel[t] = (rank < KSEL) ? (tanhf(score[t]) * (1.0f / KSEL)) : 0.0f;
    }
    __syncthreads();

    // ---- Phase J: pooled partials from registers (acc2 holds relu'd h) ----
    {
        const int rb = lane >> 2, cb = 2 * (lane & 3);
        float pp[8][2];
#pragma unroll
        for (int nt = 0; nt < 8; nt++) { pp[nt][0] = 0.f; pp[nt][1] = 0.f; }
#pragma unroll
        for (int mt = 0; mt < 2; mt++) {
            int row0 = m0 + 16 * mt + rb;
            float w0 = wsel[row0], w1 = wsel[row0 + 8];
#pragma unroll
            for (int nt = 0; nt < 8; nt++) {
                pp[nt][0] = fmaf(w0, acc2[mt][nt][0], fmaf(w1, acc2[mt][nt][2], pp[nt][0]));
                pp[nt][1] = fmaf(w0, acc2[mt][nt][1], fmaf(w1, acc2[mt][nt][3], pp[nt][1]));
            }
        }
#pragma unroll
        for (int o = 4; o <= 16; o <<= 1) {
#pragma unroll
            for (int nt = 0; nt < 8; nt++) {
                pp[nt][0] += __shfl_xor_sync(0xFFFFFFFFu, pp[nt][0], o);
                pp[nt][1] += __shfl_xor_sync(0xFFFFFFFFu, pp[nt][1], o);
            }
        }
        if (lane < 4) {
            float* dst = part2 + (warp & 3) * 128;
#pragma unroll
            for (int nt = 0; nt < 8; nt++) {
                int col = n0 + 8 * nt + cb;
                dst[col]     = pp[nt][0];
                dst[col + 1] = pp[nt][1];
            }
        }
    }
    __syncthreads();
    if (t < 128)
        pooled[t] = part2[t] + part2[128 + t] + part2[256 + t] + part2[384 + t];
    __syncthreads();

    // ---- Phase K: out = pooled @ Wlin + blin, 2 threads per f ----
    {
        int f = t & 127, hf = t >> 7;
        const float* pl = pooled + hf * 64;
        const float* wl = Wlin + hf * 64 * 128 + f;
        float o = 0.f;
#pragma unroll 16
        for (int k = 0; k < 64; k++) o = fmaf(pl[k], wl[k * 128], o);
        part[t] = o;
    }
    __syncthreads();
    if (t < 128)
        out[(size_t)g * HID + t] = part[t] + part[t + 128] + blin[t];
}

extern "C" void kernel_launch(void* const* d_in, const int* in_sizes, int n_in,
                              void* d_out, int out_size) {
    const float* x    = (const float*)d_in[0];
    const int*   ei   = (const int*)  d_in[1];
    const float* W1   = (const float*)d_in[3];
    const float* b1   = (const float*)d_in[4];
    const float* Ws   = (const float*)d_in[5];
    const float* bs   = (const float*)d_in[6];
    const float* Wlin = (const float*)d_in[7];
    const float* blin = (const float*)d_in[8];
    float* out = (float*)d_out;

    const int E = in_sizes[1] / 2;
    const int* esrc = ei;
    const int* edst = ei + E;

    cudaFuncSetAttribute(sagpool_fused_kernel,
                         cudaFuncAttributeMaxDynamicSharedMemorySize, SMEM_BYTES);
    sagpool_fused_kernel<<<NB, 256, SMEM_BYTES>>>(
        x, esrc, edst, W1, b1, Ws, bs, Wlin, blin, out);
}